// round 14
// baseline (speedup 1.0000x reference)
#include <cuda_runtime.h>

#define NN 100000

typedef unsigned long long u64;

// ---------------- scratch (device globals) ----------------
__device__ float g_hid[(size_t)NN * 64];       // leaky(pi_feat @ piw1 + pib1), node order
__device__ float g_sum[(size_t)NN * 64];       // aggregated hid over own-type in-edges
__device__ float g_hidf4[4][(size_t)NN * 64];  // b1 + feat@w1f, per class, perm order
__device__ float g_pos[NN];
__device__ float g_cnt[NN];
__device__ float g_h[(size_t)NN * 128];
__device__ int   g_np4[4];         // counts: 0=m_po 1=m_relu 2=g_po 3=g_relu
__device__ int   g_perm4[4][NN];
__device__ float g_Cm[65 * 64];    // rows 0..63: piw2 @ nm_w1_neigh; row 64: pib2 @ ...
__device__ float g_Cg[65 * 64];
__device__ float g_Dm[64 * 128];   // nm_w2 @ o_w1_h
__device__ float g_Dg[64 * 128];   // ng_w2 @ o_w1_h
__device__ float g_em[128];        // o_b1 + nm_b2 @ o_w1_h
__device__ float g_eg[128];
__device__ float g_A[65 * 128];
__device__ float g_B[65 * 128];
__device__ float g_knots[64];

__device__ __forceinline__ float leaky(float x) { return x > 0.f ? x : 0.1f * x; }

// ---- packed f32x2 helpers ----
__device__ __forceinline__ u64 pack2(float x, float y) {
    u64 r; asm("mov.b64 %0,{%1,%2};" : "=l"(r) : "f"(x), "f"(y)); return r;
}
__device__ __forceinline__ void unpack2(u64 v, float& x, float& y) {
    asm("mov.b64 {%0,%1},%2;" : "=f"(x), "=f"(y) : "l"(v));
}
__device__ __forceinline__ void fma2(u64& acc, u64 a, u64 b) {
    asm("fma.rn.f32x2 %0,%1,%2,%0;" : "+l"(acc) : "l"(a), "l"(b));
}

// one input feature per node (2 nodes) into 64-wide accumulators (32 u64 each)
__device__ __forceinline__ void l1in2(u64* ha, u64* hb, float xa_, float xb_,
                                      const float* w) {
    u64 xa = pack2(xa_, xa_), xb = pack2(xb_, xb_);
    const ulonglong2* wp = (const ulonglong2*)w;
#pragma unroll
    for (int i = 0; i < 16; i++) {
        ulonglong2 ww = wp[i];
        fma2(ha[2 * i], xa, ww.x);
        fma2(ha[2 * i + 1], xa, ww.y);
        fma2(hb[2 * i], xb, ww.x);
        fma2(hb[2 * i + 1], xb, ww.y);
    }
}

// 64 hidden (activated, packed) x 2 nodes -> 32 outputs at column j0 of [64,STRIDE]
template <int STRIDE>
__device__ __forceinline__ void layer2_chunk2(
    const u64* ha, const u64* hb, const float* w2, const float* b2, int j0,
    u64* aa, u64* ab)
{
    const u64* bp = (const u64*)(b2 + j0);
#pragma unroll
    for (int i = 0; i < 16; i++) { aa[i] = bp[i]; ab[i] = bp[i]; }
#pragma unroll 4
    for (int kk = 0; kk < 32; kk++) {
        float a0, a1, b0, b1;
        unpack2(ha[kk], a0, a1);
        unpack2(hb[kk], b0, b1);
        u64 xa0 = pack2(a0, a0), xa1 = pack2(a1, a1);
        u64 xb0 = pack2(b0, b0), xb1 = pack2(b1, b1);
        const ulonglong2* w0 = (const ulonglong2*)(w2 + (size_t)(2 * kk) * STRIDE + j0);
        const ulonglong2* w1 = (const ulonglong2*)(w2 + (size_t)(2 * kk + 1) * STRIDE + j0);
#pragma unroll
        for (int i = 0; i < 8; i++) {
            ulonglong2 w = w0[i];
            fma2(aa[2 * i], xa0, w.x); fma2(aa[2 * i + 1], xa0, w.y);
            fma2(ab[2 * i], xb0, w.x); fma2(ab[2 * i + 1], xb0, w.y);
        }
#pragma unroll
        for (int i = 0; i < 8; i++) {
            ulonglong2 w = w1[i];
            fma2(aa[2 * i], xa1, w.x); fma2(aa[2 * i + 1], xa1, w.y);
            fma2(ab[2 * i], xb1, w.x); fma2(ab[2 * i + 1], xb1, w.y);
        }
    }
}

__device__ __forceinline__ void leaky_pack(u64* h2) {
#pragma unroll
    for (int i = 0; i < 32; i++) {
        float a, b; unpack2(h2[i], a, b);
        h2[i] = pack2(leaky(a), leaky(b));
    }
}

// ---------------- KC: composed projections Cm, Cg (stream s3) ----------------
__global__ void k_compose(
    const float* __restrict__ piw2, const float* __restrict__ pib2,
    const float* __restrict__ nmw1, const float* __restrict__ ngw1)
{
    int i = blockIdx.x;       // 0..64
    int gsel = blockIdx.y;    // 0=m 1=g
    int j = threadIdx.x;      // 0..63
    const float* W = gsel ? ngw1 : nmw1;
    const float* src = (i < 64) ? (piw2 + i * 128) : pib2;
    float acc = 0.f;
#pragma unroll 8
    for (int c = 0; c < 128; c++) acc += __ldg(src + c) * __ldg(W + c * 64 + j);
    (gsel ? g_Cg : g_Cm)[i * 64 + j] = acc;
}

// ---------------- KC2: D = w2 @ o_w1_h (64x128), e = o_b1 + b2 @ o_w1_h (s3) ------
__global__ void k_compose2(
    const float* __restrict__ nm_w2, const float* __restrict__ nm_b2,
    const float* __restrict__ ng_w2, const float* __restrict__ ng_b2,
    const float* __restrict__ o_w1, const float* __restrict__ o_b1)
{
    int i = blockIdx.x;       // 0..64 (64 => e row)
    int t = blockIdx.y;       // 0=m 1=g
    int j = threadIdx.x;      // 0..127
    const float* w2 = t ? ng_w2 : nm_w2;
    const float* b2 = t ? ng_b2 : nm_b2;
    if (i < 64) {
        float acc = 0.f;
#pragma unroll 8
        for (int c = 0; c < 128; c++)
            acc += __ldg(w2 + i * 128 + c) * __ldg(o_w1 + (size_t)c * 128 + j);
        (t ? g_Dg : g_Dm)[i * 128 + j] = acc;
    } else {
        float acc = __ldg(o_b1 + j);
#pragma unroll 8
        for (int c = 0; c < 128; c++)
            acc += __ldg(b2 + c) * __ldg(o_w1 + (size_t)c * 128 + j);
        (t ? g_eg : g_em)[j] = acc;
    }
}

// ---------------- KP: 4-way partition + zero per-node scalars (side stream) ------
__global__ void k_part(const int* __restrict__ is_module,
                       const int* __restrict__ is_po, int n) {
    int i = blockIdx.x * blockDim.x + threadIdx.x;
    bool valid = i < n;
    if (valid) { g_pos[i] = 0.f; g_cnt[i] = 0.f; }
    int cls = -1;
    if (valid) cls = ((is_module[i] == 1) ? 0 : 2) + ((is_po[i] == 1) ? 0 : 1);
    int lane = threadIdx.x & 31;
    unsigned lt = (1u << lane) - 1u;
#pragma unroll
    for (int c = 0; c < 4; c++) {
        unsigned bal = __ballot_sync(0xffffffffu, cls == c);
        int b0 = 0;
        if (lane == 0 && bal) b0 = atomicAdd(&g_np4[c], __popc(bal));
        b0 = __shfl_sync(0xffffffffu, b0, 0);
        if (cls == c) g_perm4[c][b0 + __popc(bal & lt)] = i;
    }
}

// ---- block -> (segment, 512-tile) mapping over the 4 class segments ----
__device__ __forceinline__ bool seg_map512(int b, int& seg, int& tile, int& total) {
    int c0 = g_np4[0], c1 = g_np4[1], c2 = g_np4[2], c3 = g_np4[3];
    int t0 = (c0 + 511) >> 9, t1 = (c1 + 511) >> 9, t2 = (c2 + 511) >> 9;
    int t3 = (c3 + 511) >> 9;
    if (b < t0) { seg = 0; tile = b; total = c0; return true; }
    b -= t0;
    if (b < t1) { seg = 1; tile = b; total = c1; return true; }
    b -= t1;
    if (b < t2) { seg = 2; tile = b; total = c2; return true; }
    b -= t2;
    if (b < t3) { seg = 3; tile = b; total = c3; return true; }
    return false;
}

// ---------------- KF: hidf = b1_sel + feat@w1f_sel (perm order; side stream) ------
#define FEAT_SMEM ((4096 + 64) * 4)
__global__ void __launch_bounds__(128) k_feat(
    const float* __restrict__ feat,
    const float* __restrict__ nm_w1, const float* __restrict__ nm_b1,
    const float* __restrict__ ng_w1, const float* __restrict__ ng_b1)
{
    int seg, tile, total;
    if (!seg_map512(blockIdx.x, seg, tile, total)) return;
    bool MOD = seg < 2;

    const float* w1 = MOD ? nm_w1 : ng_w1;
    const float* b1 = MOD ? nm_b1 : ng_b1;
    const float* w1f = w1 + (MOD ? 129 : 128) * 64;
    const int* perm = g_perm4[seg];
    float* outb = g_hidf4[seg];

    extern __shared__ float sm[];
    for (int i = threadIdx.x; i < 4096; i += 128) sm[i] = w1f[i];
    for (int i = threadIdx.x; i < 64; i += 128) sm[4096 + i] = b1[i];
    __syncthreads();

#pragma unroll 1
    for (int sub = 0; sub < 2; sub++) {
        int p0 = tile * 512 + sub * 256 + threadIdx.x;
        if (p0 >= total) break;
        int p1 = p0 + 128;
        bool v1 = p1 < total;
        int nda = perm[p0];
        int ndb = v1 ? perm[p1] : nda;

        u64 ha[32], hb[32];
        {
            const u64* bp = (const u64*)(sm + 4096);
#pragma unroll
            for (int i = 0; i < 32; i++) { ha[i] = bp[i]; hb[i] = bp[i]; }
        }
        {
            const float4* fa = (const float4*)(feat + (size_t)nda * 64);
            const float4* fb = (const float4*)(feat + (size_t)ndb * 64);
#pragma unroll 2
            for (int k4 = 0; k4 < 16; k4++) {
                float4 va = __ldg(fa + k4);
                float4 vb = __ldg(fb + k4);
                const float* wr = sm + (k4 * 4) * 64;
                l1in2(ha, hb, va.x, vb.x, wr);
                l1in2(ha, hb, va.y, vb.y, wr + 64);
                l1in2(ha, hb, va.z, vb.z, wr + 128);
                l1in2(ha, hb, va.w, vb.w, wr + 192);
            }
        }
        u64* oa = (u64*)(outb + (size_t)p0 * 64);
#pragma unroll
        for (int i = 0; i < 32; i++) oa[i] = ha[i];
        if (v1) {
            u64* ob = (u64*)(outb + (size_t)p1 * 64);
#pragma unroll
            for (int i = 0; i < 32; i++) ob[i] = hb[i];
        }
    }
}

// ---------------- K2: fused — table (blocks<65), hid_pi (rest) ----
// pre smem: piw1 0(256) pib1 256(64) tot 320
#define PRE_SMEM (320 * 4)
__global__ void __launch_bounds__(128) k_pre(
    const float* __restrict__ pi_feat,
    const float* __restrict__ piw1, const float* __restrict__ pib1,
    const float* __restrict__ gw1, const float* __restrict__ gb1,
    const float* __restrict__ gw2, const float* __restrict__ gb2,
    const float* __restrict__ o_w1,
    const float* __restrict__ o_b2, float* __restrict__ out, int n)
{
    int b = blockIdx.x;
    if (b < 65) {
        // ---- piecewise-linear table (consumed by k_node po-path and k_out)
        __shared__ float s_t[64], s_w[64], s_b[64];
        __shared__ int s_pos[64];
        __shared__ float s_a[128], s_c[128];
        int j = threadIdx.x;
        int s = b;
        if (j < 64) {
            float w = gw1[j], bb = gb1[j];
            s_w[j] = w; s_b[j] = bb;
            s_t[j] = (w != 0.f) ? (-bb / w) : 3.0e38f;
        }
        __syncthreads();
        if (j < 64) {
            float t = s_t[j];
            int r = 0;
            for (int i = 0; i < 64; i++) {
                float ti = s_t[i];
                if (ti < t || (ti == t && i < j)) r++;
            }
            s_pos[j] = r;
        }
        __syncthreads();
        if (s == 0 && j < 64) g_knots[s_pos[j]] = s_t[j];
        {
            float a = 0.f, c = __ldg(gb2 + j);
#pragma unroll 8
            for (int k = 0; k < 64; k++) {
                float w = s_w[k], bb = s_b[k];
                bool positive = (w > 0.f) ? (s > s_pos[k])
                               : (w < 0.f) ? (s <= s_pos[k])
                               : (bb > 0.f);
                float sc = positive ? 1.0f : 0.1f;
                float gv = __ldg(gw2 + k * 128 + j);
                a += sc * w * gv;
                c += sc * bb * gv;
            }
            s_a[j] = a; s_c[j] = c;
        }
        __syncthreads();
        float A = 0.f, B = 0.f;
#pragma unroll 8
        for (int c = 0; c < 128; c++) {
            float o = __ldg(o_w1 + (size_t)(128 + c) * 128 + j);
            A += s_a[c] * o;
            B += s_c[c] * o;
        }
        g_A[s * 128 + j] = A;
        g_B[s * 128 + j] = B;
        return;
    }
    // ---- hid_pi = leaky(pi_feat @ piw1 + pib1) -> g_hid; seed out
    extern __shared__ float sm[];
    {
        int t = threadIdx.x;
        for (int i = t; i < 256; i += 128) sm[i] = piw1[i];
        for (int i = t; i < 64; i += 128) sm[256 + i] = pib1[i];
    }
    __syncthreads();

    int tile = b - 65;
    int nd0 = tile * 256 + threadIdx.x;
    if (nd0 >= n) return;
    int nd1 = nd0 + 128;
    bool v1 = nd1 < n;
    int nd1c = v1 ? nd1 : nd0;

    float ob2 = __ldg(o_b2);
    out[nd0] = ob2;
    if (v1) out[nd1] = ob2;

    float4 pa = __ldg((const float4*)pi_feat + nd0);
    float4 pb = __ldg((const float4*)pi_feat + nd1c);

    u64 ha[32], hb[32];
    {
        const u64* bp = (const u64*)(sm + 256);
#pragma unroll
        for (int i = 0; i < 32; i++) { ha[i] = bp[i]; hb[i] = bp[i]; }
        l1in2(ha, hb, pa.x, pb.x, sm + 0 * 64);
        l1in2(ha, hb, pa.y, pb.y, sm + 1 * 64);
        l1in2(ha, hb, pa.z, pb.z, sm + 2 * 64);
        l1in2(ha, hb, pa.w, pb.w, sm + 3 * 64);
        leaky_pack(ha);
        leaky_pack(hb);
    }
    u64* oa = (u64*)(g_hid + (size_t)nd0 * 64);
#pragma unroll
    for (int i = 0; i < 32; i++) oa[i] = ha[i];
    if (v1) {
        u64* ob = (u64*)(g_hid + (size_t)nd1 * 64);
#pragma unroll
        for (int i = 0; i < 32; i++) ob[i] = hb[i];
    }
}

// ---------------- K3: edges, dst-type filtered, single 64-dim hid buffer ----------
#define EPHW 4
__global__ void __launch_bounds__(256) k_edges_all(
    const int* __restrict__ src_m, const int* __restrict__ dst_m,
    const int* __restrict__ src_g, const int* __restrict__ dst_g,
    const float* __restrict__ bitpos, const int* __restrict__ is_module,
    int Em, int Eg)
{
    int l16 = threadIdx.x & 15;
    long long hw = ((long long)blockIdx.x * blockDim.x + threadIdx.x) >> 4;
    long long base = hw * EPHW;
    long long Etot = (long long)Em + Eg;
    if (base >= Etot) return;
    int cnt = (int)(Etot - base < EPHW ? Etot - base : EPHW);

    int s[EPHW], d[EPHW];
    bool ism[EPHW], keep[EPHW];
#pragma unroll
    for (int i = 0; i < EPHW; i++) {
        keep[i] = false;
        if (i < cnt) {
            long long e = base + i;
            if (e < Em) {
                ism[i] = true;
                s[i] = __ldg(src_m + e);
                d[i] = __ldg(dst_m + e);
            } else {
                ism[i] = false;
                s[i] = __ldg(src_g + (e - Em));
                d[i] = __ldg(dst_g + (e - Em));
            }
            keep[i] = ((__ldg(is_module + d[i]) == 1) == ism[i]);
        }
    }
    float4 v[EPHW];
#pragma unroll
    for (int i = 0; i < EPHW; i++)
        if (keep[i])
            v[i] = __ldg((const float4*)(g_hid + (size_t)s[i] * 64) + l16);
#pragma unroll
    for (int i = 0; i < EPHW; i++) {
        if (keep[i]) {
            float* p = g_sum + (size_t)d[i] * 64 + l16 * 4;
            asm volatile("red.global.add.v4.f32 [%0], {%1,%2,%3,%4};"
                         :: "l"(p), "f"(v[i].x), "f"(v[i].y), "f"(v[i].z), "f"(v[i].w)
                         : "memory");
            if (l16 == 0) {
                atomicAdd(g_cnt + d[i], 1.0f);
                if (ism[i]) atomicAdd(g_pos + d[i], __ldg(bitpos + base + i));
            }
        }
    }
}

// ---------------- K4: node MLP, 512-node tiles; PO finishes readout ------
// smem floats: w1pos 0(64) | C 64(4160) | W 4224(8192) | bias 12416(128) |
//              knots 12544(64) | w2o 12608(128) -> 12736 floats (50944 B)
#define NS_W1POS 0
#define NS_C 64
#define NS_W 4224
#define NS_BIAS 12416
#define NS_KN 12544
#define NS_W2O 12608
#define NODE_SMEM (12736 * 4)
__global__ void __launch_bounds__(128) k_node_all(
    const float* __restrict__ nm_w1,
    const float* __restrict__ nm_w2, const float* __restrict__ nm_b2,
    const float* __restrict__ ng_w2, const float* __restrict__ ng_b2,
    const float* __restrict__ o_w2, const float* __restrict__ level,
    float* __restrict__ out)
{
    int seg, tile, total;
    if (!seg_map512(blockIdx.x, seg, tile, total)) return;
    bool MOD = seg < 2;
    bool PO = (seg & 1) == 0;

    extern __shared__ float sm[];
    {
        int t = threadIdx.x;
        for (int i = t; i < 64; i += 128)
            sm[NS_W1POS + i] = MOD ? nm_w1[128 * 64 + i] : 0.f;
        const float* C = MOD ? g_Cm : g_Cg;
        for (int i = t; i < 4160; i += 128) sm[NS_C + i] = C[i];
        if (PO) {
            const float* D = MOD ? g_Dm : g_Dg;
            const float* e = MOD ? g_em : g_eg;
            for (int i = t; i < 8192; i += 128) sm[NS_W + i] = D[i];
            for (int i = t; i < 128; i += 128) sm[NS_BIAS + i] = e[i];
            for (int i = t; i < 64; i += 128) sm[NS_KN + i] = g_knots[i];
            for (int i = t; i < 128; i += 128) sm[NS_W2O + i] = o_w2[i];
        } else {
            const float* w2 = MOD ? nm_w2 : ng_w2;
            const float* b2 = MOD ? nm_b2 : ng_b2;
            for (int i = t; i < 8192; i += 128) sm[NS_W + i] = w2[i];
            for (int i = t; i < 128; i += 128) sm[NS_BIAS + i] = b2[i];
        }
    }
    __syncthreads();

    const int* perm = g_perm4[seg];
    const float* hidf = g_hidf4[seg];

#pragma unroll 1
    for (int sub = 0; sub < 2; sub++) {
        int p0 = tile * 512 + sub * 256 + threadIdx.x;
        if (p0 >= total) break;
        int p1 = p0 + 128;
        bool v1 = p1 < total;
        int p1c = v1 ? p1 : p0;
        int nda = perm[p0];
        int ndb = v1 ? perm[p1] : nda;

        float cnta = g_cnt[nda];
        float cntb = g_cnt[ndb];
        float inva = 1.0f / fmaxf(cnta, 1.0f);
        float invb = 1.0f / fmaxf(cntb, 1.0f);
        float facta = cnta * inva;   // 1 if cnt>0 else 0
        float factb = cntb * invb;

        const u64* hfa = (const u64*)(hidf + (size_t)p0 * 64);
        const u64* hfb = (const u64*)(hidf + (size_t)p1c * 64);

        u64 ha[32], hb[32];
#pragma unroll
        for (int i = 0; i < 32; i++) { ha[i] = hfa[i]; hb[i] = hfb[i]; }

        // constant row of C (bias of projected neighborhood), gated by cnt>0
        l1in2(ha, hb, facta, factb, sm + NS_C + 64 * 64);

        // (sum * inv) @ C[0:64]
        {
            const float4* sa4 = (const float4*)(g_sum + (size_t)nda * 64);
            const float4* sb4 = (const float4*)(g_sum + (size_t)ndb * 64);
#pragma unroll 2
            for (int k4 = 0; k4 < 16; k4++) {
                float4 va = __ldg(sa4 + k4);
                float4 vb = __ldg(sb4 + k4);
                const float* wr = sm + NS_C + (k4 * 4) * 64;
                l1in2(ha, hb, va.x * inva, vb.x * invb, wr);
                l1in2(ha, hb, va.y * inva, vb.y * invb, wr + 64);
                l1in2(ha, hb, va.z * inva, vb.z * invb, wr + 128);
                l1in2(ha, hb, va.w * inva, vb.w * invb, wr + 192);
            }
        }
        if (MOD) {
            float posa = g_pos[nda] * inva;
            float posb = g_pos[ndb] * invb;
            l1in2(ha, hb, posa, posb, sm + NS_W1POS);
        }
        leaky_pack(ha);
        leaky_pack(hb);

        u64 aa[16], ab[16];
        if (PO) {
            float lva = __ldg(level + nda);
            float lvb = __ldg(level + ndb);
            int sa = 0, sb = 0;
#pragma unroll
            for (int k = 0; k < 64; k++) {
                float kn = sm[NS_KN + k];
                sa += (kn < lva) ? 1 : 0;
                sb += (kn < lvb) ? 1 : 0;
            }
            const float4* A4a = (const float4*)(g_A + sa * 128);
            const float4* B4a = (const float4*)(g_B + sa * 128);
            const float4* A4b = (const float4*)(g_A + sb * 128);
            const float4* B4b = (const float4*)(g_B + sb * 128);
            float ra = 0.f, rb = 0.f;
#pragma unroll 1
            for (int c = 0; c < 4; c++) {
                layer2_chunk2<128>(ha, hb, sm + NS_W, sm + NS_BIAS, c * 32, aa, ab);
#pragma unroll
                for (int q = 0; q < 8; q++) {
                    int j = c * 32 + q * 4;
                    float4 av = __ldg(A4a + c * 8 + q);
                    float4 bv = __ldg(B4a + c * 8 + q);
                    float x, y;
                    unpack2(aa[2 * q], x, y);
                    x += fmaf(av.x, lva, bv.x);
                    y += fmaf(av.y, lva, bv.y);
                    ra += leaky(x) * sm[NS_W2O + j] + leaky(y) * sm[NS_W2O + j + 1];
                    unpack2(aa[2 * q + 1], x, y);
                    x += fmaf(av.z, lva, bv.z);
                    y += fmaf(av.w, lva, bv.w);
                    ra += leaky(x) * sm[NS_W2O + j + 2] + leaky(y) * sm[NS_W2O + j + 3];

                    float4 av2 = __ldg(A4b + c * 8 + q);
                    float4 bv2 = __ldg(B4b + c * 8 + q);
                    unpack2(ab[2 * q], x, y);
                    x += fmaf(av2.x, lvb, bv2.x);
                    y += fmaf(av2.y, lvb, bv2.y);
                    rb += leaky(x) * sm[NS_W2O + j] + leaky(y) * sm[NS_W2O + j + 1];
                    unpack2(ab[2 * q + 1], x, y);
                    x += fmaf(av2.z, lvb, bv2.z);
                    y += fmaf(av2.w, lvb, bv2.w);
                    rb += leaky(x) * sm[NS_W2O + j + 2] + leaky(y) * sm[NS_W2O + j + 3];
                }
            }
            atomicAdd(out + nda, ra);
            if (v1) atomicAdd(out + ndb, rb);
        } else {
            float* ora = g_h + (size_t)nda * 128;
            float* orb = g_h + (size_t)ndb * 128;
#pragma unroll 1
            for (int c = 0; c < 4; c++) {
                layer2_chunk2<128>(ha, hb, sm + NS_W, sm + NS_BIAS, c * 32, aa, ab);
                u64* oa = (u64*)(ora + c * 32);
#pragma unroll
                for (int i = 0; i < 16; i++) {
                    float x, y; unpack2(aa[i], x, y);
                    oa[i] = pack2(fmaxf(x, 0.f), fmaxf(y, 0.f));
                }
                if (v1) {
                    u64* ob = (u64*)(orb + c * 32);
#pragma unroll
                    for (int i = 0; i < 16; i++) {
                        float x, y; unpack2(ab[i], x, y);
                        ob[i] = pack2(fmaxf(x, 0.f), fmaxf(y, 0.f));
                    }
                }
            }
        }
    }
}

// ---------------- K5: readout for relu nodes only, hidden-half split, 512-tiles ---
// smem floats: w1h 0..8191 | A 8192 (65*66=4290) | B 12482 (4290) |
//              b1 16772(64) | w2 16836(64) | knots 16900(64) -> 16964 floats
#define SM_A 8192
#define SM_B 12482
#define SM_B1 16772
#define SM_W2 16836
#define SM_KN 16900
#define OUT_SMEM (16964 * 4)
__global__ void __launch_bounds__(128) k_out(
    const float* __restrict__ o_w1, const float* __restrict__ o_b1,
    const float* __restrict__ o_w2, const float* __restrict__ level,
    float* __restrict__ out)
{
    int half = blockIdx.x & 1;
    int tb = blockIdx.x >> 1;
    int c1 = g_np4[1], c3 = g_np4[3];
    int t1 = (c1 + 511) >> 9;
    int seg, tile, total;
    if (tb < t1) { seg = 1; tile = tb; total = c1; }
    else {
        tb -= t1;
        if (tb >= ((c3 + 511) >> 9)) return;
        seg = 3; tile = tb; total = c3;
    }

    extern __shared__ float sm[];
    for (int i = threadIdx.x; i < 8192; i += 128) {
        int row = i >> 6, col = i & 63;
        sm[i] = o_w1[row * 128 + half * 64 + col];
    }
    for (int i = threadIdx.x; i < 65 * 64; i += 128) {
        int sg = i >> 6, col = i & 63;
        sm[SM_A + sg * 66 + col] = g_A[sg * 128 + half * 64 + col];
        sm[SM_B + sg * 66 + col] = g_B[sg * 128 + half * 64 + col];
    }
    for (int i = threadIdx.x; i < 64; i += 128) {
        sm[SM_B1 + i] = o_b1[half * 64 + i];
        sm[SM_W2 + i] = o_w2[half * 64 + i];
        sm[SM_KN + i] = g_knots[i];
    }
    __syncthreads();

    const int* perm = g_perm4[seg];

#pragma unroll 1
    for (int sub = 0; sub < 2; sub++) {
        int p0 = tile * 512 + sub * 256 + threadIdx.x;
        if (p0 >= total) break;
        int p1 = p0 + 128;
        bool v1 = p1 < total;
        int nd0 = perm[p0];
        int nd1 = v1 ? perm[p1] : nd0;

        float lva = __ldg(level + nd0);
        float lvb = __ldg(level + nd1);
        int sa = 0, sb = 0;
#pragma unroll
        for (int k = 0; k < 64; k++) {
            float kn = sm[SM_KN + k];
            sa += (kn < lva) ? 1 : 0;
            sb += (kn < lvb) ? 1 : 0;
        }

        u64 aa[32], ab[32];
        {
            const float* Aa = sm + SM_A + sa * 66;
            const float* Ba = sm + SM_B + sa * 66;
            const float* Ab = sm + SM_A + sb * 66;
            const float* Bb = sm + SM_B + sb * 66;
            const float* br = sm + SM_B1;
#pragma unroll
            for (int i = 0; i < 32; i++) {
                float a0 = fmaf(Aa[2 * i], lva, br[2 * i] + Ba[2 * i]);
                float a1 = fmaf(Aa[2 * i + 1], lva, br[2 * i + 1] + Ba[2 * i + 1]);
                aa[i] = pack2(a0, a1);
                float b0 = fmaf(Ab[2 * i], lvb, br[2 * i] + Bb[2 * i]);
                float b1 = fmaf(Ab[2 * i + 1], lvb, br[2 * i + 1] + Bb[2 * i + 1]);
                ab[i] = pack2(b0, b1);
            }
        }
        const float4* xa = (const float4*)(g_h + (size_t)nd0 * 128);
        const float4* xb = (const float4*)(g_h + (size_t)nd1 * 128);
#pragma unroll 2
        for (int k4 = 0; k4 < 32; k4++) {
            float4 va = __ldg(xa + k4);
            float4 vb = __ldg(xb + k4);
            const float* wr = sm + (k4 * 4) * 64;
            l1in2(aa, ab, va.x, vb.x, wr);
            l1in2(aa, ab, va.y, vb.y, wr + 64);
            l1in2(aa, ab, va.z, vb.z, wr + 128);
            l1in2(aa, ab, va.w, vb.w, wr + 192);
        }
        float ra = 0.f, rb = 0.f;
#pragma unroll
        for (int i = 0; i < 32; i++) {
            float x, y; unpack2(aa[i], x, y);
            ra += leaky(x) * sm[SM_W2 + 2 * i] + leaky(y) * sm[SM_W2 + 2 * i + 1];
            unpack2(ab[i], x, y);
            rb += leaky(x) * sm[SM_W2 + 2 * i] + leaky(y) * sm[SM_W2 + 2 * i + 1];
        }
        atomicAdd(out + nd0, ra);
        if (v1) atomicAdd(out + nd1, rb);
    }
}

// ---------------- host launch ----------------
extern "C" void kernel_launch(void* const* d_in, const int* in_sizes, int n_in,
                              void* d_out, int out_size)
{
    const float* feat    = (const float*)d_in[0];
    const float* pi_feat = (const float*)d_in[1];
    const float* level   = (const float*)d_in[2];
    const float* bitpos  = (const float*)d_in[3];

    const int *is_po, *is_module, *src_m, *dst_m, *src_g, *dst_g;
    const float *pi_w1, *pi_b1, *pi_w2, *pi_b2;
    const float *nm_w1, *nm_b1, *nm_w2, *nm_b2;
    const float *ng_w1, *ng_b1, *ng_w2, *ng_b2;
    const float *gw1, *gb1, *gw2, *gb2;
    const float *o_w1, *o_b1, *o_w2, *o_b2;
    int Em, Eg;

    if (in_sizes[4] < 1000) {
        // reference-signature order
        pi_w1 = (const float*)d_in[4];  pi_b1 = (const float*)d_in[5];
        pi_w2 = (const float*)d_in[6];  pi_b2 = (const float*)d_in[7];
        nm_w1 = (const float*)d_in[8];  nm_b1 = (const float*)d_in[9];
        nm_w2 = (const float*)d_in[10]; nm_b2 = (const float*)d_in[11];
        ng_w1 = (const float*)d_in[12]; ng_b1 = (const float*)d_in[13];
        ng_w2 = (const float*)d_in[14]; ng_b2 = (const float*)d_in[15];
        gw1 = (const float*)d_in[16];   gb1 = (const float*)d_in[17];
        gw2 = (const float*)d_in[18];   gb2 = (const float*)d_in[19];
        o_w1 = (const float*)d_in[20];  o_b1 = (const float*)d_in[21];
        o_w2 = (const float*)d_in[22];  o_b2 = (const float*)d_in[23];
        is_po = (const int*)d_in[24];   is_module = (const int*)d_in[25];
        src_m = (const int*)d_in[26];   dst_m = (const int*)d_in[27];
        src_g = (const int*)d_in[28];   dst_g = (const int*)d_in[29];
        Em = in_sizes[26]; Eg = in_sizes[28];
    } else {
        // setup_inputs dict order
        is_po = (const int*)d_in[4];    is_module = (const int*)d_in[5];
        src_m = (const int*)d_in[6];    dst_m = (const int*)d_in[7];
        src_g = (const int*)d_in[8];    dst_g = (const int*)d_in[9];
        pi_w1 = (const float*)d_in[10]; pi_b1 = (const float*)d_in[11];
        pi_w2 = (const float*)d_in[12]; pi_b2 = (const float*)d_in[13];
        nm_w1 = (const float*)d_in[14]; nm_b1 = (const float*)d_in[15];
        nm_w2 = (const float*)d_in[16]; nm_b2 = (const float*)d_in[17];
        ng_w1 = (const float*)d_in[18]; ng_b1 = (const float*)d_in[19];
        ng_w2 = (const float*)d_in[20]; ng_b2 = (const float*)d_in[21];
        gw1 = (const float*)d_in[22];   gb1 = (const float*)d_in[23];
        gw2 = (const float*)d_in[24];   gb2 = (const float*)d_in[25];
        o_w1 = (const float*)d_in[26];  o_b1 = (const float*)d_in[27];
        o_w2 = (const float*)d_in[28];  o_b2 = (const float*)d_in[29];
        Em = in_sizes[6]; Eg = in_sizes[8];
    }

    int n = in_sizes[2];  // level has N elements

    // one-time resources (host-side; no device allocation)
    static cudaStream_t s2 = nullptr, s3 = nullptr;
    static cudaEvent_t evFork = nullptr, evZero = nullptr, evB = nullptr, evC = nullptr;
    if (!s2) {
        cudaStreamCreate(&s2);
        cudaStreamCreate(&s3);
        cudaEventCreateWithFlags(&evFork, cudaEventDisableTiming);
        cudaEventCreateWithFlags(&evZero, cudaEventDisableTiming);
        cudaEventCreateWithFlags(&evB, cudaEventDisableTiming);
        cudaEventCreateWithFlags(&evC, cudaEventDisableTiming);
    }

    cudaFuncSetAttribute(k_pre, cudaFuncAttributeMaxDynamicSharedMemorySize, PRE_SMEM);
    cudaFuncSetAttribute(k_feat, cudaFuncAttributeMaxDynamicSharedMemorySize, FEAT_SMEM);
    cudaFuncSetAttribute(k_node_all, cudaFuncAttributeMaxDynamicSharedMemorySize, NODE_SMEM);
    cudaFuncSetAttribute(k_out, cudaFuncAttributeMaxDynamicSharedMemorySize, OUT_SMEM);

    int ntile = (n + 255) / 256;          // 256-node tiles (k_pre)
    int ntile512 = (n + 511) / 512;       // 512-node tiles (k_feat/k_node/k_out)
    int npart = (n + 255) / 256;

    void *p_sum, *p_np;
    cudaGetSymbolAddress(&p_sum, g_sum);
    cudaGetSymbolAddress(&p_np, g_np4);

    // fork side streams into capture
    cudaEventRecord(evFork, 0);
    cudaStreamWaitEvent(s2, evFork, 0);
    cudaStreamWaitEvent(s3, evFork, 0);

    // ---- stream s3: weight-only composes (no data deps)
    k_compose<<<dim3(65, 2), 64, 0, s3>>>(pi_w2, pi_b2, nm_w1, ng_w1);
    k_compose2<<<dim3(65, 2), 128, 0, s3>>>(nm_w2, nm_b2, ng_w2, ng_b2, o_w1, o_b1);
    cudaEventRecord(evC, s3);

    // ---- stream s2: zero + partition + feat projection
    cudaMemsetAsync(p_sum, 0, (size_t)n * 64 * 4, s2);
    cudaMemsetAsync(p_np, 0, 16, s2);
    k_part<<<npart, 256, 0, s2>>>(is_module, is_po, n);
    cudaEventRecord(evZero, s2);    // sums + per-node scalars all zeroed
    k_feat<<<ntile512 + 4, 128, FEAT_SMEM, s2>>>(feat, nm_w1, nm_b1, ng_w1, ng_b1);
    cudaEventRecord(evB, s2);

    // ---- main stream A
    k_pre<<<65 + ntile, 128, PRE_SMEM>>>(
        pi_feat, pi_w1, pi_b1,
        gw1, gb1, gw2, gb2, o_w1,
        o_b2, (float*)d_out, n);

    cudaStreamWaitEvent(0, evZero, 0);
    long long Etot = (long long)Em + Eg;
    long long hws = (Etot + EPHW - 1) / EPHW;
    int eb = (int)((hws * 16 + 255) / 256);
    k_edges_all<<<eb, 256>>>(src_m, dst_m, src_g, dst_g, bitpos, is_module, Em, Eg);

    cudaStreamWaitEvent(0, evB, 0);
    cudaStreamWaitEvent(0, evC, 0);
    k_node_all<<<ntile512 + 4, 128, NODE_SMEM>>>(
        nm_w1, nm_w2, nm_b2, ng_w2, ng_b2, o_w2, level, (float*)d_out);

    k_out<<<(ntile512 + 2) * 2, 128, OUT_SMEM>>>(
        o_w1, o_b1, o_w2, level, (float*)d_out);
}

// round 15
// speedup vs baseline: 1.0753x; 1.0753x over previous
#include <cuda_runtime.h>

#define NN 100000

typedef unsigned long long u64;

// ---------------- scratch (device globals) ----------------
__device__ float g_hid[(size_t)NN * 64];       // leaky(pi_feat @ piw1 + pib1), node order
__device__ float g_sum[(size_t)NN * 64];       // aggregated hid over own-type in-edges
__device__ float g_hidf4[4][(size_t)NN * 64];  // b1 + feat@w1f, per class, perm order
__device__ float g_pos[NN];
__device__ float g_cnt[NN];
__device__ float g_h[(size_t)NN * 128];
__device__ int   g_np4[4];         // counts: 0=m_po 1=m_relu 2=g_po 3=g_relu
__device__ int   g_perm4[4][NN];
__device__ float g_Cm[65 * 64];    // rows 0..63: piw2 @ nm_w1_neigh; row 64: pib2 @ ...
__device__ float g_Cg[65 * 64];
__device__ float g_Dm[64 * 128];   // nm_w2 @ o_w1_h
__device__ float g_Dg[64 * 128];   // ng_w2 @ o_w1_h
__device__ float g_em[128];        // o_b1 + nm_b2 @ o_w1_h
__device__ float g_eg[128];
__device__ float g_A[65 * 128];
__device__ float g_B[65 * 128];
__device__ float g_knots[64];

__device__ __forceinline__ float leaky(float x) { return x > 0.f ? x : 0.1f * x; }

// ---- packed f32x2 helpers ----
__device__ __forceinline__ u64 pack2(float x, float y) {
    u64 r; asm("mov.b64 %0,{%1,%2};" : "=l"(r) : "f"(x), "f"(y)); return r;
}
__device__ __forceinline__ void unpack2(u64 v, float& x, float& y) {
    asm("mov.b64 {%0,%1},%2;" : "=f"(x), "=f"(y) : "l"(v));
}
__device__ __forceinline__ void fma2(u64& acc, u64 a, u64 b) {
    asm("fma.rn.f32x2 %0,%1,%2,%0;" : "+l"(acc) : "l"(a), "l"(b));
}

// one input feature per node (2 nodes) into 64-wide accumulators (32 u64 each)
__device__ __forceinline__ void l1in2(u64* ha, u64* hb, float xa_, float xb_,
                                      const float* w) {
    u64 xa = pack2(xa_, xa_), xb = pack2(xb_, xb_);
    const ulonglong2* wp = (const ulonglong2*)w;
#pragma unroll
    for (int i = 0; i < 16; i++) {
        ulonglong2 ww = wp[i];
        fma2(ha[2 * i], xa, ww.x);
        fma2(ha[2 * i + 1], xa, ww.y);
        fma2(hb[2 * i], xb, ww.x);
        fma2(hb[2 * i + 1], xb, ww.y);
    }
}

// 64 hidden (activated, packed) x 2 nodes -> 32 outputs at column j0 of [64,STRIDE]
template <int STRIDE>
__device__ __forceinline__ void layer2_chunk2(
    const u64* ha, const u64* hb, const float* w2, const float* b2, int j0,
    u64* aa, u64* ab)
{
    const u64* bp = (const u64*)(b2 + j0);
#pragma unroll
    for (int i = 0; i < 16; i++) { aa[i] = bp[i]; ab[i] = bp[i]; }
#pragma unroll 4
    for (int kk = 0; kk < 32; kk++) {
        float a0, a1, b0, b1;
        unpack2(ha[kk], a0, a1);
        unpack2(hb[kk], b0, b1);
        u64 xa0 = pack2(a0, a0), xa1 = pack2(a1, a1);
        u64 xb0 = pack2(b0, b0), xb1 = pack2(b1, b1);
        const ulonglong2* w0 = (const ulonglong2*)(w2 + (size_t)(2 * kk) * STRIDE + j0);
        const ulonglong2* w1 = (const ulonglong2*)(w2 + (size_t)(2 * kk + 1) * STRIDE + j0);
#pragma unroll
        for (int i = 0; i < 8; i++) {
            ulonglong2 w = w0[i];
            fma2(aa[2 * i], xa0, w.x); fma2(aa[2 * i + 1], xa0, w.y);
            fma2(ab[2 * i], xb0, w.x); fma2(ab[2 * i + 1], xb0, w.y);
        }
#pragma unroll
        for (int i = 0; i < 8; i++) {
            ulonglong2 w = w1[i];
            fma2(aa[2 * i], xa1, w.x); fma2(aa[2 * i + 1], xa1, w.y);
            fma2(ab[2 * i], xb1, w.x); fma2(ab[2 * i + 1], xb1, w.y);
        }
    }
}

__device__ __forceinline__ void leaky_pack(u64* h2) {
#pragma unroll
    for (int i = 0; i < 32; i++) {
        float a, b; unpack2(h2[i], a, b);
        h2[i] = pack2(leaky(a), leaky(b));
    }
}

// ---------------- KC: composed projections Cm, Cg (stream s3) ----------------
__global__ void k_compose(
    const float* __restrict__ piw2, const float* __restrict__ pib2,
    const float* __restrict__ nmw1, const float* __restrict__ ngw1)
{
    int i = blockIdx.x;       // 0..64
    int gsel = blockIdx.y;    // 0=m 1=g
    int j = threadIdx.x;      // 0..63
    const float* W = gsel ? ngw1 : nmw1;
    const float* src = (i < 64) ? (piw2 + i * 128) : pib2;
    float acc = 0.f;
#pragma unroll 8
    for (int c = 0; c < 128; c++) acc += __ldg(src + c) * __ldg(W + c * 64 + j);
    (gsel ? g_Cg : g_Cm)[i * 64 + j] = acc;
}

// ---------------- KC2: D = w2 @ o_w1_h (64x128), e = o_b1 + b2 @ o_w1_h (s3) ------
__global__ void k_compose2(
    const float* __restrict__ nm_w2, const float* __restrict__ nm_b2,
    const float* __restrict__ ng_w2, const float* __restrict__ ng_b2,
    const float* __restrict__ o_w1, const float* __restrict__ o_b1)
{
    int i = blockIdx.x;       // 0..64 (64 => e row)
    int t = blockIdx.y;       // 0=m 1=g
    int j = threadIdx.x;      // 0..127
    const float* w2 = t ? ng_w2 : nm_w2;
    const float* b2 = t ? ng_b2 : nm_b2;
    if (i < 64) {
        float acc = 0.f;
#pragma unroll 8
        for (int c = 0; c < 128; c++)
            acc += __ldg(w2 + i * 128 + c) * __ldg(o_w1 + (size_t)c * 128 + j);
        (t ? g_Dg : g_Dm)[i * 128 + j] = acc;
    } else {
        float acc = __ldg(o_b1 + j);
#pragma unroll 8
        for (int c = 0; c < 128; c++)
            acc += __ldg(b2 + c) * __ldg(o_w1 + (size_t)c * 128 + j);
        (t ? g_eg : g_em)[j] = acc;
    }
}

// ---------------- KP: 4-way partition + zero per-node scalars (side stream) ------
__global__ void k_part(const int* __restrict__ is_module,
                       const int* __restrict__ is_po, int n) {
    int i = blockIdx.x * blockDim.x + threadIdx.x;
    bool valid = i < n;
    if (valid) { g_pos[i] = 0.f; g_cnt[i] = 0.f; }
    int cls = -1;
    if (valid) cls = ((is_module[i] == 1) ? 0 : 2) + ((is_po[i] == 1) ? 0 : 1);
    int lane = threadIdx.x & 31;
    unsigned lt = (1u << lane) - 1u;
#pragma unroll
    for (int c = 0; c < 4; c++) {
        unsigned bal = __ballot_sync(0xffffffffu, cls == c);
        int b0 = 0;
        if (lane == 0 && bal) b0 = atomicAdd(&g_np4[c], __popc(bal));
        b0 = __shfl_sync(0xffffffffu, b0, 0);
        if (cls == c) g_perm4[c][b0 + __popc(bal & lt)] = i;
    }
}

// ---- block -> (segment, tile) mapping over the 4 class segments (256-tiles) ----
__device__ __forceinline__ bool seg_map(int b, int& seg, int& tile, int& total) {
    int c0 = g_np4[0], c1 = g_np4[1], c2 = g_np4[2], c3 = g_np4[3];
    int t0 = (c0 + 255) >> 8, t1 = (c1 + 255) >> 8, t2 = (c2 + 255) >> 8;
    int t3 = (c3 + 255) >> 8;
    if (b < t0) { seg = 0; tile = b; total = c0; return true; }
    b -= t0;
    if (b < t1) { seg = 1; tile = b; total = c1; return true; }
    b -= t1;
    if (b < t2) { seg = 2; tile = b; total = c2; return true; }
    b -= t2;
    if (b < t3) { seg = 3; tile = b; total = c3; return true; }
    return false;
}

// ---------------- KF: hidf = b1_sel + feat@w1f_sel (perm order; side stream) ------
#define FEAT_SMEM ((4096 + 64) * 4)
__global__ void __launch_bounds__(128) k_feat(
    const float* __restrict__ feat,
    const float* __restrict__ nm_w1, const float* __restrict__ nm_b1,
    const float* __restrict__ ng_w1, const float* __restrict__ ng_b1)
{
    int seg, tile, total;
    if (!seg_map(blockIdx.x, seg, tile, total)) return;
    bool MOD = seg < 2;

    const float* w1 = MOD ? nm_w1 : ng_w1;
    const float* b1 = MOD ? nm_b1 : ng_b1;
    const float* w1f = w1 + (MOD ? 129 : 128) * 64;
    const int* perm = g_perm4[seg];
    float* outb = g_hidf4[seg];

    extern __shared__ float sm[];
    for (int i = threadIdx.x; i < 4096; i += 128) sm[i] = w1f[i];
    for (int i = threadIdx.x; i < 64; i += 128) sm[4096 + i] = b1[i];
    __syncthreads();

    int p0 = tile * 256 + threadIdx.x;
    if (p0 >= total) return;
    int p1 = p0 + 128;
    bool v1 = p1 < total;
    int nda = perm[p0];
    int ndb = v1 ? perm[p1] : nda;

    u64 ha[32], hb[32];
    {
        const u64* bp = (const u64*)(sm + 4096);
#pragma unroll
        for (int i = 0; i < 32; i++) { ha[i] = bp[i]; hb[i] = bp[i]; }
    }
    {
        const float4* fa = (const float4*)(feat + (size_t)nda * 64);
        const float4* fb = (const float4*)(feat + (size_t)ndb * 64);
#pragma unroll 2
        for (int k4 = 0; k4 < 16; k4++) {
            float4 va = __ldg(fa + k4);
            float4 vb = __ldg(fb + k4);
            const float* wr = sm + (k4 * 4) * 64;
            l1in2(ha, hb, va.x, vb.x, wr);
            l1in2(ha, hb, va.y, vb.y, wr + 64);
            l1in2(ha, hb, va.z, vb.z, wr + 128);
            l1in2(ha, hb, va.w, vb.w, wr + 192);
        }
    }
    u64* oa = (u64*)(outb + (size_t)p0 * 64);
#pragma unroll
    for (int i = 0; i < 32; i++) oa[i] = ha[i];
    if (v1) {
        u64* ob = (u64*)(outb + (size_t)p1 * 64);
#pragma unroll
        for (int i = 0; i < 32; i++) ob[i] = hb[i];
    }
}

// ---------------- K2: fused — table (blocks<65), hid_pi (rest) ----
// pre smem: piw1 0(256) pib1 256(64) tot 320
#define PRE_SMEM (320 * 4)
__global__ void __launch_bounds__(128) k_pre(
    const float* __restrict__ pi_feat,
    const float* __restrict__ piw1, const float* __restrict__ pib1,
    const float* __restrict__ gw1, const float* __restrict__ gb1,
    const float* __restrict__ gw2, const float* __restrict__ gb2,
    const float* __restrict__ o_w1,
    const float* __restrict__ o_b2, float* __restrict__ out, int n)
{
    int b = blockIdx.x;
    if (b < 65) {
        // ---- piecewise-linear table (consumed by k_node po-path and k_out)
        __shared__ float s_t[64], s_w[64], s_b[64];
        __shared__ int s_pos[64];
        __shared__ float s_a[128], s_c[128];
        int j = threadIdx.x;
        int s = b;
        if (j < 64) {
            float w = gw1[j], bb = gb1[j];
            s_w[j] = w; s_b[j] = bb;
            s_t[j] = (w != 0.f) ? (-bb / w) : 3.0e38f;
        }
        __syncthreads();
        if (j < 64) {
            float t = s_t[j];
            int r = 0;
            for (int i = 0; i < 64; i++) {
                float ti = s_t[i];
                if (ti < t || (ti == t && i < j)) r++;
            }
            s_pos[j] = r;
        }
        __syncthreads();
        if (s == 0 && j < 64) g_knots[s_pos[j]] = s_t[j];
        {
            float a = 0.f, c = __ldg(gb2 + j);
#pragma unroll 8
            for (int k = 0; k < 64; k++) {
                float w = s_w[k], bb = s_b[k];
                bool positive = (w > 0.f) ? (s > s_pos[k])
                               : (w < 0.f) ? (s <= s_pos[k])
                               : (bb > 0.f);
                float sc = positive ? 1.0f : 0.1f;
                float gv = __ldg(gw2 + k * 128 + j);
                a += sc * w * gv;
                c += sc * bb * gv;
            }
            s_a[j] = a; s_c[j] = c;
        }
        __syncthreads();
        float A = 0.f, B = 0.f;
#pragma unroll 8
        for (int c = 0; c < 128; c++) {
            float o = __ldg(o_w1 + (size_t)(128 + c) * 128 + j);
            A += s_a[c] * o;
            B += s_c[c] * o;
        }
        g_A[s * 128 + j] = A;
        g_B[s * 128 + j] = B;
        return;
    }
    // ---- hid_pi = leaky(pi_feat @ piw1 + pib1) -> g_hid; seed out
    extern __shared__ float sm[];
    {
        int t = threadIdx.x;
        for (int i = t; i < 256; i += 128) sm[i] = piw1[i];
        for (int i = t; i < 64; i += 128) sm[256 + i] = pib1[i];
    }
    __syncthreads();

    int tile = b - 65;
    int nd0 = tile * 256 + threadIdx.x;
    if (nd0 >= n) return;
    int nd1 = nd0 + 128;
    bool v1 = nd1 < n;
    int nd1c = v1 ? nd1 : nd0;

    float ob2 = __ldg(o_b2);
    out[nd0] = ob2;
    if (v1) out[nd1] = ob2;

    float4 pa = __ldg((const float4*)pi_feat + nd0);
    float4 pb = __ldg((const float4*)pi_feat + nd1c);

    u64 ha[32], hb[32];
    {
        const u64* bp = (const u64*)(sm + 256);
#pragma unroll
        for (int i = 0; i < 32; i++) { ha[i] = bp[i]; hb[i] = bp[i]; }
        l1in2(ha, hb, pa.x, pb.x, sm + 0 * 64);
        l1in2(ha, hb, pa.y, pb.y, sm + 1 * 64);
        l1in2(ha, hb, pa.z, pb.z, sm + 2 * 64);
        l1in2(ha, hb, pa.w, pb.w, sm + 3 * 64);
        leaky_pack(ha);
        leaky_pack(hb);
    }
    u64* oa = (u64*)(g_hid + (size_t)nd0 * 64);
#pragma unroll
    for (int i = 0; i < 32; i++) oa[i] = ha[i];
    if (v1) {
        u64* ob = (u64*)(g_hid + (size_t)nd1 * 64);
#pragma unroll
        for (int i = 0; i < 32; i++) ob[i] = hb[i];
    }
}

// ---------------- K3: edges, dst-type filtered, single 64-dim hid buffer ----------
#define EPHW 4
__global__ void __launch_bounds__(256) k_edges_all(
    const int* __restrict__ src_m, const int* __restrict__ dst_m,
    const int* __restrict__ src_g, const int* __restrict__ dst_g,
    const float* __restrict__ bitpos, const int* __restrict__ is_module,
    int Em, int Eg)
{
    int l16 = threadIdx.x & 15;
    long long hw = ((long long)blockIdx.x * blockDim.x + threadIdx.x) >> 4;
    long long base = hw * EPHW;
    long long Etot = (long long)Em + Eg;
    if (base >= Etot) return;
    int cnt = (int)(Etot - base < EPHW ? Etot - base : EPHW);

    int s[EPHW], d[EPHW];
    bool ism[EPHW], keep[EPHW];
#pragma unroll
    for (int i = 0; i < EPHW; i++) {
        keep[i] = false;
        if (i < cnt) {
            long long e = base + i;
            if (e < Em) {
                ism[i] = true;
                s[i] = __ldg(src_m + e);
                d[i] = __ldg(dst_m + e);
            } else {
                ism[i] = false;
                s[i] = __ldg(src_g + (e - Em));
                d[i] = __ldg(dst_g + (e - Em));
            }
            keep[i] = ((__ldg(is_module + d[i]) == 1) == ism[i]);
        }
    }
    float4 v[EPHW];
#pragma unroll
    for (int i = 0; i < EPHW; i++)
        if (keep[i])
            v[i] = __ldg((const float4*)(g_hid + (size_t)s[i] * 64) + l16);
#pragma unroll
    for (int i = 0; i < EPHW; i++) {
        if (keep[i]) {
            float* p = g_sum + (size_t)d[i] * 64 + l16 * 4;
            asm volatile("red.global.add.v4.f32 [%0], {%1,%2,%3,%4};"
                         :: "l"(p), "f"(v[i].x), "f"(v[i].y), "f"(v[i].z), "f"(v[i].w)
                         : "memory");
            if (l16 == 0) {
                atomicAdd(g_cnt + d[i], 1.0f);
                if (ism[i]) atomicAdd(g_pos + d[i], __ldg(bitpos + base + i));
            }
        }
    }
}

// ---------------- K4: node MLP with dst-side projection; PO finishes readout ------
// smem floats: w1pos 0(64) | C 64(4160) | W 4224(8192) | bias 12416(128) |
//              knots 12544(64) | w2o 12608(128) -> 12736 floats (50944 B)
#define NS_W1POS 0
#define NS_C 64
#define NS_W 4224
#define NS_BIAS 12416
#define NS_KN 12544
#define NS_W2O 12608
#define NODE_SMEM (12736 * 4)
__global__ void __launch_bounds__(128) k_node_all(
    const float* __restrict__ nm_w1,
    const float* __restrict__ nm_w2, const float* __restrict__ nm_b2,
    const float* __restrict__ ng_w2, const float* __restrict__ ng_b2,
    const float* __restrict__ o_w2, const float* __restrict__ level,
    float* __restrict__ out)
{
    int seg, tile, total;
    if (!seg_map(blockIdx.x, seg, tile, total)) return;
    bool MOD = seg < 2;
    bool PO = (seg & 1) == 0;

    extern __shared__ float sm[];
    {
        int t = threadIdx.x;
        for (int i = t; i < 64; i += 128)
            sm[NS_W1POS + i] = MOD ? nm_w1[128 * 64 + i] : 0.f;
        const float* C = MOD ? g_Cm : g_Cg;
        for (int i = t; i < 4160; i += 128) sm[NS_C + i] = C[i];
        if (PO) {
            const float* D = MOD ? g_Dm : g_Dg;
            const float* e = MOD ? g_em : g_eg;
            for (int i = t; i < 8192; i += 128) sm[NS_W + i] = D[i];
            for (int i = t; i < 128; i += 128) sm[NS_BIAS + i] = e[i];
            for (int i = t; i < 64; i += 128) sm[NS_KN + i] = g_knots[i];
            for (int i = t; i < 128; i += 128) sm[NS_W2O + i] = o_w2[i];
        } else {
            const float* w2 = MOD ? nm_w2 : ng_w2;
            const float* b2 = MOD ? nm_b2 : ng_b2;
            for (int i = t; i < 8192; i += 128) sm[NS_W + i] = w2[i];
            for (int i = t; i < 128; i += 128) sm[NS_BIAS + i] = b2[i];
        }
    }
    __syncthreads();

    int p0 = tile * 256 + threadIdx.x;
    if (p0 >= total) return;
    int p1 = p0 + 128;
    bool v1 = p1 < total;
    int p1c = v1 ? p1 : p0;
    const int* perm = g_perm4[seg];
    int nda = perm[p0];
    int ndb = v1 ? perm[p1] : nda;

    const float* hidf = g_hidf4[seg];

    float cnta = g_cnt[nda];
    float cntb = g_cnt[ndb];
    float inva = 1.0f / fmaxf(cnta, 1.0f);
    float invb = 1.0f / fmaxf(cntb, 1.0f);
    float facta = cnta * inva;   // 1 if cnt>0 else 0
    float factb = cntb * invb;

    const u64* hfa = (const u64*)(hidf + (size_t)p0 * 64);
    const u64* hfb = (const u64*)(hidf + (size_t)p1c * 64);

    u64 ha[32], hb[32];
#pragma unroll
    for (int i = 0; i < 32; i++) { ha[i] = hfa[i]; hb[i] = hfb[i]; }

    // constant row of C (bias of projected neighborhood), gated by cnt>0
    l1in2(ha, hb, facta, factb, sm + NS_C + 64 * 64);

    // (sum * inv) @ C[0:64]
    {
        const float4* sa4 = (const float4*)(g_sum + (size_t)nda * 64);
        const float4* sb4 = (const float4*)(g_sum + (size_t)ndb * 64);
#pragma unroll 2
        for (int k4 = 0; k4 < 16; k4++) {
            float4 va = __ldg(sa4 + k4);
            float4 vb = __ldg(sb4 + k4);
            const float* wr = sm + NS_C + (k4 * 4) * 64;
            l1in2(ha, hb, va.x * inva, vb.x * invb, wr);
            l1in2(ha, hb, va.y * inva, vb.y * invb, wr + 64);
            l1in2(ha, hb, va.z * inva, vb.z * invb, wr + 128);
            l1in2(ha, hb, va.w * inva, vb.w * invb, wr + 192);
        }
    }
    if (MOD) {
        float posa = g_pos[nda] * inva;
        float posb = g_pos[ndb] * invb;
        l1in2(ha, hb, posa, posb, sm + NS_W1POS);
    }
    leaky_pack(ha);
    leaky_pack(hb);

    u64 aa[16], ab[16];
    if (PO) {
        float lva = __ldg(level + nda);
        float lvb = __ldg(level + ndb);
        int sa = 0, sb = 0;
#pragma unroll
        for (int k = 0; k < 64; k++) {
            float kn = sm[NS_KN + k];
            sa += (kn < lva) ? 1 : 0;
            sb += (kn < lvb) ? 1 : 0;
        }
        const float4* A4a = (const float4*)(g_A + sa * 128);
        const float4* B4a = (const float4*)(g_B + sa * 128);
        const float4* A4b = (const float4*)(g_A + sb * 128);
        const float4* B4b = (const float4*)(g_B + sb * 128);
        float ra = 0.f, rb = 0.f;
#pragma unroll 1
        for (int c = 0; c < 4; c++) {
            layer2_chunk2<128>(ha, hb, sm + NS_W, sm + NS_BIAS, c * 32, aa, ab);
#pragma unroll
            for (int q = 0; q < 8; q++) {
                int j = c * 32 + q * 4;
                float4 av = __ldg(A4a + c * 8 + q);
                float4 bv = __ldg(B4a + c * 8 + q);
                float x, y;
                unpack2(aa[2 * q], x, y);
                x += fmaf(av.x, lva, bv.x);
                y += fmaf(av.y, lva, bv.y);
                ra += leaky(x) * sm[NS_W2O + j] + leaky(y) * sm[NS_W2O + j + 1];
                unpack2(aa[2 * q + 1], x, y);
                x += fmaf(av.z, lva, bv.z);
                y += fmaf(av.w, lva, bv.w);
                ra += leaky(x) * sm[NS_W2O + j + 2] + leaky(y) * sm[NS_W2O + j + 3];

                float4 av2 = __ldg(A4b + c * 8 + q);
                float4 bv2 = __ldg(B4b + c * 8 + q);
                unpack2(ab[2 * q], x, y);
                x += fmaf(av2.x, lvb, bv2.x);
                y += fmaf(av2.y, lvb, bv2.y);
                rb += leaky(x) * sm[NS_W2O + j] + leaky(y) * sm[NS_W2O + j + 1];
                unpack2(ab[2 * q + 1], x, y);
                x += fmaf(av2.z, lvb, bv2.z);
                y += fmaf(av2.w, lvb, bv2.w);
                rb += leaky(x) * sm[NS_W2O + j + 2] + leaky(y) * sm[NS_W2O + j + 3];
            }
        }
        atomicAdd(out + nda, ra);
        if (v1) atomicAdd(out + ndb, rb);
    } else {
        float* ora = g_h + (size_t)nda * 128;
        float* orb = g_h + (size_t)ndb * 128;
#pragma unroll 1
        for (int c = 0; c < 4; c++) {
            layer2_chunk2<128>(ha, hb, sm + NS_W, sm + NS_BIAS, c * 32, aa, ab);
            u64* oa = (u64*)(ora + c * 32);
#pragma unroll
            for (int i = 0; i < 16; i++) {
                float x, y; unpack2(aa[i], x, y);
                oa[i] = pack2(fmaxf(x, 0.f), fmaxf(y, 0.f));
            }
            if (v1) {
                u64* ob = (u64*)(orb + c * 32);
#pragma unroll
                for (int i = 0; i < 16; i++) {
                    float x, y; unpack2(ab[i], x, y);
                    ob[i] = pack2(fmaxf(x, 0.f), fmaxf(y, 0.f));
                }
            }
        }
    }
}

// ---------------- K5: readout for relu nodes only, hidden-half split --------------
// smem floats: w1h 0..8191 | A 8192 (65*66=4290) | B 12482 (4290) |
//              b1 16772(64) | w2 16836(64) | knots 16900(64) -> 16964 floats
#define SM_A 8192
#define SM_B 12482
#define SM_B1 16772
#define SM_W2 16836
#define SM_KN 16900
#define OUT_SMEM (16964 * 4)
__global__ void __launch_bounds__(128) k_out(
    const float* __restrict__ o_w1, const float* __restrict__ o_b1,
    const float* __restrict__ o_w2, const float* __restrict__ level,
    float* __restrict__ out)
{
    int half = blockIdx.x & 1;
    int tb = blockIdx.x >> 1;
    int c1 = g_np4[1], c3 = g_np4[3];
    int t1 = (c1 + 255) >> 8;
    int seg, tile, total;
    if (tb < t1) { seg = 1; tile = tb; total = c1; }
    else {
        tb -= t1;
        if (tb >= ((c3 + 255) >> 8)) return;
        seg = 3; tile = tb; total = c3;
    }

    extern __shared__ float sm[];
    for (int i = threadIdx.x; i < 8192; i += 128) {
        int row = i >> 6, col = i & 63;
        sm[i] = o_w1[row * 128 + half * 64 + col];
    }
    for (int i = threadIdx.x; i < 65 * 64; i += 128) {
        int sg = i >> 6, col = i & 63;
        sm[SM_A + sg * 66 + col] = g_A[sg * 128 + half * 64 + col];
        sm[SM_B + sg * 66 + col] = g_B[sg * 128 + half * 64 + col];
    }
    for (int i = threadIdx.x; i < 64; i += 128) {
        sm[SM_B1 + i] = o_b1[half * 64 + i];
        sm[SM_W2 + i] = o_w2[half * 64 + i];
        sm[SM_KN + i] = g_knots[i];
    }
    __syncthreads();

    int p0 = tile * 256 + threadIdx.x;
    if (p0 >= total) return;
    int p1 = p0 + 128;
    bool v1 = p1 < total;
    const int* perm = g_perm4[seg];
    int nd0 = perm[p0];
    int nd1 = v1 ? perm[p1] : nd0;

    float lva = __ldg(level + nd0);
    float lvb = __ldg(level + nd1);
    int sa = 0, sb = 0;
#pragma unroll
    for (int k = 0; k < 64; k++) {
        float kn = sm[SM_KN + k];
        sa += (kn < lva) ? 1 : 0;
        sb += (kn < lvb) ? 1 : 0;
    }

    u64 aa[32], ab[32];
    {
        const float* Aa = sm + SM_A + sa * 66;
        const float* Ba = sm + SM_B + sa * 66;
        const float* Ab = sm + SM_A + sb * 66;
        const float* Bb = sm + SM_B + sb * 66;
        const float* br = sm + SM_B1;
#pragma unroll
        for (int i = 0; i < 32; i++) {
            float a0 = fmaf(Aa[2 * i], lva, br[2 * i] + Ba[2 * i]);
            float a1 = fmaf(Aa[2 * i + 1], lva, br[2 * i + 1] + Ba[2 * i + 1]);
            aa[i] = pack2(a0, a1);
            float b0 = fmaf(Ab[2 * i], lvb, br[2 * i] + Bb[2 * i]);
            float b1 = fmaf(Ab[2 * i + 1], lvb, br[2 * i + 1] + Bb[2 * i + 1]);
            ab[i] = pack2(b0, b1);
        }
    }
    const float4* xa = (const float4*)(g_h + (size_t)nd0 * 128);
    const float4* xb = (const float4*)(g_h + (size_t)nd1 * 128);
#pragma unroll 2
    for (int k4 = 0; k4 < 32; k4++) {
        float4 va = __ldg(xa + k4);
        float4 vb = __ldg(xb + k4);
        const float* wr = sm + (k4 * 4) * 64;
        l1in2(aa, ab, va.x, vb.x, wr);
        l1in2(aa, ab, va.y, vb.y, wr + 64);
        l1in2(aa, ab, va.z, vb.z, wr + 128);
        l1in2(aa, ab, va.w, vb.w, wr + 192);
    }
    float ra = 0.f, rb = 0.f;
#pragma unroll
    for (int i = 0; i < 32; i++) {
        float x, y; unpack2(aa[i], x, y);
        ra += leaky(x) * sm[SM_W2 + 2 * i] + leaky(y) * sm[SM_W2 + 2 * i + 1];
        unpack2(ab[i], x, y);
        rb += leaky(x) * sm[SM_W2 + 2 * i] + leaky(y) * sm[SM_W2 + 2 * i + 1];
    }
    atomicAdd(out + nd0, ra);
    if (v1) atomicAdd(out + nd1, rb);
}

// ---------------- host launch ----------------
extern "C" void kernel_launch(void* const* d_in, const int* in_sizes, int n_in,
                              void* d_out, int out_size)
{
    const float* feat    = (const float*)d_in[0];
    const float* pi_feat = (const float*)d_in[1];
    const float* level   = (const float*)d_in[2];
    const float* bitpos  = (const float*)d_in[3];

    const int *is_po, *is_module, *src_m, *dst_m, *src_g, *dst_g;
    const float *pi_w1, *pi_b1, *pi_w2, *pi_b2;
    const float *nm_w1, *nm_b1, *nm_w2, *nm_b2;
    const float *ng_w1, *ng_b1, *ng_w2, *ng_b2;
    const float *gw1, *gb1, *gw2, *gb2;
    const float *o_w1, *o_b1, *o_w2, *o_b2;
    int Em, Eg;

    if (in_sizes[4] < 1000) {
        // reference-signature order
        pi_w1 = (const float*)d_in[4];  pi_b1 = (const float*)d_in[5];
        pi_w2 = (const float*)d_in[6];  pi_b2 = (const float*)d_in[7];
        nm_w1 = (const float*)d_in[8];  nm_b1 = (const float*)d_in[9];
        nm_w2 = (const float*)d_in[10]; nm_b2 = (const float*)d_in[11];
        ng_w1 = (const float*)d_in[12]; ng_b1 = (const float*)d_in[13];
        ng_w2 = (const float*)d_in[14]; ng_b2 = (const float*)d_in[15];
        gw1 = (const float*)d_in[16];   gb1 = (const float*)d_in[17];
        gw2 = (const float*)d_in[18];   gb2 = (const float*)d_in[19];
        o_w1 = (const float*)d_in[20];  o_b1 = (const float*)d_in[21];
        o_w2 = (const float*)d_in[22];  o_b2 = (const float*)d_in[23];
        is_po = (const int*)d_in[24];   is_module = (const int*)d_in[25];
        src_m = (const int*)d_in[26];   dst_m = (const int*)d_in[27];
        src_g = (const int*)d_in[28];   dst_g = (const int*)d_in[29];
        Em = in_sizes[26]; Eg = in_sizes[28];
    } else {
        // setup_inputs dict order
        is_po = (const int*)d_in[4];    is_module = (const int*)d_in[5];
        src_m = (const int*)d_in[6];    dst_m = (const int*)d_in[7];
        src_g = (const int*)d_in[8];    dst_g = (const int*)d_in[9];
        pi_w1 = (const float*)d_in[10]; pi_b1 = (const float*)d_in[11];
        pi_w2 = (const float*)d_in[12]; pi_b2 = (const float*)d_in[13];
        nm_w1 = (const float*)d_in[14]; nm_b1 = (const float*)d_in[15];
        nm_w2 = (const float*)d_in[16]; nm_b2 = (const float*)d_in[17];
        ng_w1 = (const float*)d_in[18]; ng_b1 = (const float*)d_in[19];
        ng_w2 = (const float*)d_in[20]; ng_b2 = (const float*)d_in[21];
        gw1 = (const float*)d_in[22];   gb1 = (const float*)d_in[23];
        gw2 = (const float*)d_in[24];   gb2 = (const float*)d_in[25];
        o_w1 = (const float*)d_in[26];  o_b1 = (const float*)d_in[27];
        o_w2 = (const float*)d_in[28];  o_b2 = (const float*)d_in[29];
        Em = in_sizes[6]; Eg = in_sizes[8];
    }

    int n = in_sizes[2];  // level has N elements

    // one-time resources (host-side; no device allocation)
    static cudaStream_t s2 = nullptr, s3 = nullptr;
    static cudaEvent_t evFork = nullptr, evZero = nullptr, evB = nullptr, evC = nullptr;
    if (!s2) {
        cudaStreamCreate(&s2);
        cudaStreamCreate(&s3);
        cudaEventCreateWithFlags(&evFork, cudaEventDisableTiming);
        cudaEventCreateWithFlags(&evZero, cudaEventDisableTiming);
        cudaEventCreateWithFlags(&evB, cudaEventDisableTiming);
        cudaEventCreateWithFlags(&evC, cudaEventDisableTiming);
    }

    cudaFuncSetAttribute(k_pre, cudaFuncAttributeMaxDynamicSharedMemorySize, PRE_SMEM);
    cudaFuncSetAttribute(k_feat, cudaFuncAttributeMaxDynamicSharedMemorySize, FEAT_SMEM);
    cudaFuncSetAttribute(k_node_all, cudaFuncAttributeMaxDynamicSharedMemorySize, NODE_SMEM);
    cudaFuncSetAttribute(k_out, cudaFuncAttributeMaxDynamicSharedMemorySize, OUT_SMEM);

    int ntile = (n + 255) / 256;          // 256-node tiles
    int npart = (n + 255) / 256;

    void *p_sum, *p_np;
    cudaGetSymbolAddress(&p_sum, g_sum);
    cudaGetSymbolAddress(&p_np, g_np4);

    // fork side streams into capture
    cudaEventRecord(evFork, 0);
    cudaStreamWaitEvent(s2, evFork, 0);
    cudaStreamWaitEvent(s3, evFork, 0);

    // ---- stream s3: weight-only composes (no data deps)
    k_compose<<<dim3(65, 2), 64, 0, s3>>>(pi_w2, pi_b2, nm_w1, ng_w1);
    k_compose2<<<dim3(65, 2), 128, 0, s3>>>(nm_w2, nm_b2, ng_w2, ng_b2, o_w1, o_b1);
    cudaEventRecord(evC, s3);

    // ---- stream s2: zero + partition + feat projection
    cudaMemsetAsync(p_sum, 0, (size_t)n * 64 * 4, s2);
    cudaMemsetAsync(p_np, 0, 16, s2);
    k_part<<<npart, 256, 0, s2>>>(is_module, is_po, n);
    cudaEventRecord(evZero, s2);    // sums + per-node scalars all zeroed
    k_feat<<<ntile + 4, 128, FEAT_SMEM, s2>>>(feat, nm_w1, nm_b1, ng_w1, ng_b1);
    cudaEventRecord(evB, s2);

    // ---- main stream A
    k_pre<<<65 + ntile, 128, PRE_SMEM>>>(
        pi_feat, pi_w1, pi_b1,
        gw1, gb1, gw2, gb2, o_w1,
        o_b2, (float*)d_out, n);

    cudaStreamWaitEvent(0, evZero, 0);
    long long Etot = (long long)Em + Eg;
    long long hws = (Etot + EPHW - 1) / EPHW;
    int eb = (int)((hws * 16 + 255) / 256);
    k_edges_all<<<eb, 256>>>(src_m, dst_m, src_g, dst_g, bitpos, is_module, Em, Eg);

    cudaStreamWaitEvent(0, evB, 0);
    cudaStreamWaitEvent(0, evC, 0);
    k_node_all<<<ntile + 4, 128, NODE_SMEM>>>(
        nm_w1, nm_w2, nm_b2, ng_w2, ng_b2, o_w2, level, (float*)d_out);

    k_out<<<(ntile + 2) * 2, 128, OUT_SMEM>>>(
        o_w1, o_b1, o_w2, level, (float*)d_out);
}

// round 16
// speedup vs baseline: 1.2000x; 1.1159x over previous
#include <cuda_runtime.h>

#define NN 100000

typedef unsigned long long u64;

__device__ float g_hid[(size_t)NN * 64];
__device__ float g_sum[(size_t)NN * 64];
__device__ float g_hidf4[4][(size_t)NN * 64];
__device__ float g_pos[NN];
__device__ float g_cnt[NN];
__device__ float g_h[(size_t)NN * 128];
__device__ int   g_np4[4];
__device__ int   g_perm4[4][NN];
__device__ float g_Cm[65 * 64];
__device__ float g_Cg[65 * 64];
__device__ float g_Dm[64 * 128];
__device__ float g_Dg[64 * 128];
__device__ float g_em[128];
__device__ float g_eg[128];
__device__ float g_A[65 * 128];
__device__ float g_B[65 * 128];
__device__ float g_knots[64];

__device__ __forceinline__ float leaky(float x) { return x > 0.f ? x : 0.1f * x; }

__device__ __forceinline__ u64 pack2(float x, float y) {
    u64 r; asm("mov.b64 %0,{%1,%2};" : "=l"(r) : "f"(x), "f"(y)); return r;
}
__device__ __forceinline__ void unpack2(u64 v, float& x, float& y) {
    asm("mov.b64 {%0,%1},%2;" : "=f"(x), "=f"(y) : "l"(v));
}
__device__ __forceinline__ void fma2(u64& acc, u64 a, u64 b) {
    asm("fma.rn.f32x2 %0,%1,%2,%0;" : "+l"(acc) : "l"(a), "l"(b));
}

__device__ __forceinline__ void l1in2(u64* ha, u64* hb, float xa_, float xb_,
                                      const float* w) {
    u64 xa = pack2(xa_, xa_), xb = pack2(xb_, xb_);
    const ulonglong2* wp = (const ulonglong2*)w;
#pragma unroll
    for (int i = 0; i < 16; i++) {
        ulonglong2 ww = wp[i];
        fma2(ha[2 * i], xa, ww.x);
        fma2(ha[2 * i + 1], xa, ww.y);
        fma2(hb[2 * i], xb, ww.x);
        fma2(hb[2 * i + 1], xb, ww.y);
    }
}

template <int STRIDE>
__device__ __forceinline__ void layer2_chunk2(
    const u64* ha, const u64* hb, const float* w2, const float* b2, int j0,
    u64* aa, u64* ab)
{
    const u64* bp = (const u64*)(b2 + j0);
#pragma unroll
    for (int i = 0; i < 16; i++) { aa[i] = bp[i]; ab[i] = bp[i]; }
#pragma unroll 4
    for (int kk = 0; kk < 32; kk++) {
        float a0, a1, b0, b1;
        unpack2(ha[kk], a0, a1);
        unpack2(hb[kk], b0, b1);
        u64 xa0 = pack2(a0, a0), xa1 = pack2(a1, a1);
        u64 xb0 = pack2(b0, b0), xb1 = pack2(b1, b1);
        const ulonglong2* w0 = (const ulonglong2*)(w2 + (size_t)(2 * kk) * STRIDE + j0);
        const ulonglong2* w1 = (const ulonglong2*)(w2 + (size_t)(2 * kk + 1) * STRIDE + j0);
#pragma unroll
        for (int i = 0; i < 8; i++) {
            ulonglong2 w = w0[i];
            fma2(aa[2 * i], xa0, w.x); fma2(aa[2 * i + 1], xa0, w.y);
            fma2(ab[2 * i], xb0, w.x); fma2(ab[2 * i + 1], xb0, w.y);
        }
#pragma unroll
        for (int i = 0; i < 8; i++) {
            ulonglong2 w = w1[i];
            fma2(aa[2 * i], xa1, w.x); fma2(aa[2 * i + 1], xa1, w.y);
            fma2(ab[2 * i], xb1, w.x); fma2(ab[2 * i + 1], xb1, w.y);
        }
    }
}

__device__ __forceinline__ void leaky_pack(u64* h2) {
#pragma unroll
    for (int i = 0; i < 32; i++) {
        float a, b; unpack2(h2[i], a, b);
        h2[i] = pack2(leaky(a), leaky(b));
    }
}

__global__ void k_compose(
    const float* __restrict__ piw2, const float* __restrict__ pib2,
    const float* __restrict__ nmw1, const float* __restrict__ ngw1)
{
    int i = blockIdx.x;
    int gsel = blockIdx.y;
    int j = threadIdx.x;
    const float* W = gsel ? ngw1 : nmw1;
    const float* src = (i < 64) ? (piw2 + i * 128) : pib2;
    float acc = 0.f;
#pragma unroll 8
    for (int c = 0; c < 128; c++) acc += __ldg(src + c) * __ldg(W + c * 64 + j);
    (gsel ? g_Cg : g_Cm)[i * 64 + j] = acc;
}

__global__ void k_compose2(
    const float* __restrict__ nm_w2, const float* __restrict__ nm_b2,
    const float* __restrict__ ng_w2, const float* __restrict__ ng_b2,
    const float* __restrict__ o_w1, const float* __restrict__ o_b1)
{
    int i = blockIdx.x;
    int t = blockIdx.y;
    int j = threadIdx.x;
    const float* w2 = t ? ng_w2 : nm_w2;
    const float* b2 = t ? ng_b2 : nm_b2;
    if (i < 64) {
        float acc = 0.f;
#pragma unroll 8
        for (int c = 0; c < 128; c++)
            acc += __ldg(w2 + i * 128 + c) * __ldg(o_w1 + (size_t)c * 128 + j);
        (t ? g_Dg : g_Dm)[i * 128 + j] = acc;
    } else {
        float acc = __ldg(o_b1 + j);
#pragma unroll 8
        for (int c = 0; c < 128; c++)
            acc += __ldg(b2 + c) * __ldg(o_w1 + (size_t)c * 128 + j);
        (t ? g_eg : g_em)[j] = acc;
    }
}

__global__ void k_part(const int* __restrict__ is_module,
                       const int* __restrict__ is_po, int n) {
    int i = blockIdx.x * blockDim.x + threadIdx.x;
    bool valid = i < n;
    if (valid) { g_pos[i] = 0.f; g_cnt[i] = 0.f; }
    int cls = -1;
    if (valid) cls = ((is_module[i] == 1) ? 0 : 2) + ((is_po[i] == 1) ? 0 : 1);
    int lane = threadIdx.x & 31;
    unsigned lt = (1u << lane) - 1u;
#pragma unroll
    for (int c = 0; c < 4; c++) {
        unsigned bal = __ballot_sync(0xffffffffu, cls == c);
        int b0 = 0;
        if (lane == 0 && bal) b0 = atomicAdd(&g_np4[c], __popc(bal));
        b0 = __shfl_sync(0xffffffffu, b0, 0);
        if (cls == c) g_perm4[c][b0 + __popc(bal & lt)] = i;
    }
}

__device__ __forceinline__ bool seg_map(int b, int& seg, int& tile, int& total) {
    int c0 = g_np4[0], c1 = g_np4[1], c2 = g_np4[2], c3 = g_np4[3];
    int t0 = (c0 + 255) >> 8, t1 = (c1 + 255) >> 8, t2 = (c2 + 255) >> 8;
    int t3 = (c3 + 255) >> 8;
    if (b < t0) { seg = 0; tile = b; total = c0; return true; }
    b -= t0;
    if (b < t1) { seg = 1; tile = b; total = c1; return true; }
    b -= t1;
    if (b < t2) { seg = 2; tile = b; total = c2; return true; }
    b -= t2;
    if (b < t3) { seg = 3; tile = b; total = c3; return true; }
    return false;
}

__device__ __forceinline__ bool seg_map2(int b, int s0, int s1,
                                         int& seg, int& tile, int& total) {
    int cA = g_np4[s0], cB = g_np4[s1];
    int tA = (cA + 255) >> 8;
    if (b < tA) { seg = s0; tile = b; total = cA; return true; }
    b -= tA;
    if (b < ((cB + 255) >> 8)) { seg = s1; tile = b; total = cB; return true; }
    return false;
}

#define FEAT_SMEM ((4096 + 64) * 4)
__global__ void __launch_bounds__(128) k_feat(
    const float* __restrict__ feat,
    const float* __restrict__ nm_w1, const float* __restrict__ nm_b1,
    const float* __restrict__ ng_w1, const float* __restrict__ ng_b1)
{
    int seg, tile, total;
    if (!seg_map(blockIdx.x, seg, tile, total)) return;
    bool MOD = seg < 2;

    const float* w1 = MOD ? nm_w1 : ng_w1;
    const float* b1 = MOD ? nm_b1 : ng_b1;
    const float* w1f = w1 + (MOD ? 129 : 128) * 64;
    const int* perm = g_perm4[seg];
    float* outb = g_hidf4[seg];

    extern __shared__ float sm[];
    for (int i = threadIdx.x; i < 4096; i += 128) sm[i] = w1f[i];
    for (int i = threadIdx.x; i < 64; i += 128) sm[4096 + i] = b1[i];
    __syncthreads();

    int p0 = tile * 256 + threadIdx.x;
    if (p0 >= total) return;
    int p1 = p0 + 128;
    bool v1 = p1 < total;
    int nda = perm[p0];
    int ndb = v1 ? perm[p1] : nda;

    u64 ha[32], hb[32];
    {
        const u64* bp = (const u64*)(sm + 4096);
#pragma unroll
        for (int i = 0; i < 32; i++) { ha[i] = bp[i]; hb[i] = bp[i]; }
    }
    {
        const float4* fa = (const float4*)(feat + (size_t)nda * 64);
        const float4* fb = (const float4*)(feat + (size_t)ndb * 64);
#pragma unroll 2
        for (int k4 = 0; k4 < 16; k4++) {
            float4 va = __ldg(fa + k4);
            float4 vb = __ldg(fb + k4);
            const float* wr = sm + (k4 * 4) * 64;
            l1in2(ha, hb, va.x, vb.x, wr);
            l1in2(ha, hb, va.y, vb.y, wr + 64);
            l1in2(ha, hb, va.z, vb.z, wr + 128);
            l1in2(ha, hb, va.w, vb.w, wr + 192);
        }
    }
    u64* oa = (u64*)(outb + (size_t)p0 * 64);
#pragma unroll
    for (int i = 0; i < 32; i++) oa[i] = ha[i];
    if (v1) {
        u64* ob = (u64*)(outb + (size_t)p1 * 64);
#pragma unroll
        for (int i = 0; i < 32; i++) ob[i] = hb[i];
    }
}

#define PRE_SMEM (320 * 4)
__global__ void __launch_bounds__(128) k_pre(
    const float* __restrict__ pi_feat,
    const float* __restrict__ piw1, const float* __restrict__ pib1,
    const float* __restrict__ gw1, const float* __restrict__ gb1,
    const float* __restrict__ gw2, const float* __restrict__ gb2,
    const float* __restrict__ o_w1,
    const float* __restrict__ o_b2, float* __restrict__ out, int n)
{
    int b = blockIdx.x;
    if (b < 65) {
        __shared__ float s_t[64], s_w[64], s_b[64];
        __shared__ int s_pos[64];
        __shared__ float s_a[128], s_c[128];
        int j = threadIdx.x;
        int s = b;
        if (j < 64) {
            float w = gw1[j], bb = gb1[j];
            s_w[j] = w; s_b[j] = bb;
            s_t[j] = (w != 0.f) ? (-bb / w) : 3.0e38f;
        }
        __syncthreads();
        if (j < 64) {
            float t = s_t[j];
            int r = 0;
            for (int i = 0; i < 64; i++) {
                float ti = s_t[i];
                if (ti < t || (ti == t && i < j)) r++;
            }
            s_pos[j] = r;
        }
        __syncthreads();
        if (s == 0 && j < 64) g_knots[s_pos[j]] = s_t[j];
        {
            float a = 0.f, c = __ldg(gb2 + j);
#pragma unroll 8
            for (int k = 0; k < 64; k++) {
                float w = s_w[k], bb = s_b[k];
                bool positive = (w > 0.f) ? (s > s_pos[k])
                               : (w < 0.f) ? (s <= s_pos[k])
                               : (bb > 0.f);
                float sc = positive ? 1.0f : 0.1f;
                float gv = __ldg(gw2 + k * 128 + j);
                a += sc * w * gv;
                c += sc * bb * gv;
            }
            s_a[j] = a; s_c[j] = c;
        }
        __syncthreads();
        float A = 0.f, B = 0.f;
#pragma unroll 8
        for (int c = 0; c < 128; c++) {
            float o = __ldg(o_w1 + (size_t)(128 + c) * 128 + j);
            A += s_a[c] * o;
            B += s_c[c] * o;
        }
        g_A[s * 128 + j] = A;
        g_B[s * 128 + j] = B;
        return;
    }
    extern __shared__ float sm[];
    {
        int t = threadIdx.x;
        for (int i = t; i < 256; i += 128) sm[i] = piw1[i];
        for (int i = t; i < 64; i += 128) sm[256 + i] = pib1[i];
    }
    __syncthreads();

    int tile = b - 65;
    int nd0 = tile * 256 + threadIdx.x;
    if (nd0 >= n) return;
    int nd1 = nd0 + 128;
    bool v1 = nd1 < n;
    int nd1c = v1 ? nd1 : nd0;

    float ob2 = __ldg(o_b2);
    out[nd0] = ob2;
    if (v1) out[nd1] = ob2;

    float4 pa = __ldg((const float4*)pi_feat + nd0);
    float4 pb = __ldg((const float4*)pi_feat + nd1c);

    u64 ha[32], hb[32];
    {
        const u64* bp = (const u64*)(sm + 256);
#pragma unroll
        for (int i = 0; i < 32; i++) { ha[i] = bp[i]; hb[i] = bp[i]; }
        l1in2(ha, hb, pa.x, pb.x, sm + 0 * 64);
        l1in2(ha, hb, pa.y, pb.y, sm + 1 * 64);
        l1in2(ha, hb, pa.z, pb.z, sm + 2 * 64);
        l1in2(ha, hb, pa.w, pb.w, sm + 3 * 64);
        leaky_pack(ha);
        leaky_pack(hb);
    }
    u64* oa = (u64*)(g_hid + (size_t)nd0 * 64);
#pragma unroll
    for (int i = 0; i < 32; i++) oa[i] = ha[i];
    if (v1) {
        u64* ob = (u64*)(g_hid + (size_t)nd1 * 64);
#pragma unroll
        for (int i = 0; i < 32; i++) ob[i] = hb[i];
    }
}

#define EPHW 4
__global__ void __launch_bounds__(256) k_edges_all(
    const int* __restrict__ src_m, const int* __restrict__ dst_m,
    const int* __restrict__ src_g, const int* __restrict__ dst_g,
    const float* __restrict__ bitpos, const int* __restrict__ is_module,
    int Em, int Eg)
{
    int l16 = threadIdx.x & 15;
    long long hw = ((long long)blockIdx.x * blockDim.x + threadIdx.x) >> 4;
    long long base = hw * EPHW;
    long long Etot = (long long)Em + Eg;
    if (base >= Etot) return;
    int cnt = (int)(Etot - base < EPHW ? Etot - base : EPHW);

    int s[EPHW], d[EPHW];
    bool ism[EPHW], keep[EPHW];
#pragma unroll
    for (int i = 0; i < EPHW; i++) {
        keep[i] = false;
        if (i < cnt) {
            long long e = base + i;
            if (e < Em) {
                ism[i] = true;
                s[i] = __ldg(src_m + e);
                d[i] = __ldg(dst_m + e);
            } else {
                ism[i] = false;
                s[i] = __ldg(src_g + (e - Em));
                d[i] = __ldg(dst_g + (e - Em));
            }
            keep[i] = ((__ldg(is_module + d[i]) == 1) == ism[i]);
        }
    }
    float4 v[EPHW];
#pragma unroll
    for (int i = 0; i < EPHW; i++)
        if (keep[i])
            v[i] = __ldg((const float4*)(g_hid + (size_t)s[i] * 64) + l16);
#pragma unroll
    for (int i = 0; i < EPHW; i++) {
        if (keep[i]) {
            float* p = g_sum + (size_t)d[i] * 64 + l16 * 4;
            asm volatile("red.global.add.v4.f32 [%0], {%1,%2,%3,%4};"
                         :: "l"(p), "f"(v[i].x), "f"(v[i].y), "f"(v[i].z), "f"(v[i].w)
                         : "memory");
            if (l16 == 0) {
                atomicAdd(g_cnt + d[i], 1.0f);
                if (ism[i]) atomicAdd(g_pos + d[i], __ldg(bitpos + base + i));
            }
        }
    }
}

#define NS_W1POS 0
#define NS_C 64
#define NS_W 4224
#define NS_BIAS 12416
#define NS_KN 12544
#define NS_W2O 12608
#define NODE_SMEM (12736 * 4)
template <bool PO>
__global__ void __launch_bounds__(128) k_node_half(
    const float* __restrict__ nm_w1,
    const float* __restrict__ nm_w2, const float* __restrict__ nm_b2,
    const float* __restrict__ ng_w2, const float* __restrict__ ng_b2,
    const float* __restrict__ o_w2, const float* __restrict__ level,
    float* __restrict__ out)
{
    int seg, tile, total;
    if (!seg_map2(blockIdx.x, PO ? 0 : 1, PO ? 2 : 3, seg, tile, total)) return;
    bool MOD = seg < 2;

    extern __shared__ float sm[];
    {
        int t = threadIdx.x;
        for (int i = t; i < 64; i += 128)
            sm[NS_W1POS + i] = MOD ? nm_w1[128 * 64 + i] : 0.f;
        const float* C = MOD ? g_Cm : g_Cg;
        for (int i = t; i < 4160; i += 128) sm[NS_C + i] = C[i];
        if (PO) {
            const float* D = MOD ? g_Dm : g_Dg;
            const float* e = MOD ? g_em : g_eg;
            for (int i = t; i < 8192; i += 128) sm[NS_W + i] = D[i];
            for (int i = t; i < 128; i += 128) sm[NS_BIAS + i] = e[i];
            for (int i = t; i < 64; i += 128) sm[NS_KN + i] = g_knots[i];
            for (int i = t; i < 128; i += 128) sm[NS_W2O + i] = o_w2[i];
        } else {
            const float* w2 = MOD ? nm_w2 : ng_w2;
            const float* b2 = MOD ? nm_b2 : ng_b2;
            for (int i = t; i < 8192; i += 128) sm[NS_W + i] = w2[i];
            for (int i = t; i < 128; i += 128) sm[NS_BIAS + i] = b2[i];
        }
    }
    __syncthreads();

    int p0 = tile * 256 + threadIdx.x;
    if (p0 >= total) return;
    int p1 = p0 + 128;
    bool v1 = p1 < total;
    int p1c = v1 ? p1 : p0;
    const int* perm = g_perm4[seg];
    int nda = perm[p0];
    int ndb = v1 ? perm[p1] : nda;

    const float* hidf = g_hidf4[seg];

    float cnta = g_cnt[nda];
    float cntb = g_cnt[ndb];
    float inva = 1.0f / fmaxf(cnta, 1.0f);
    float invb = 1.0f / fmaxf(cntb, 1.0f);
    float facta = cnta * inva;
    float factb = cntb * invb;

    const u64* hfa = (const u64*)(hidf + (size_t)p0 * 64);
    const u64* hfb = (const u64*)(hidf + (size_t)p1c * 64);

    u64 ha[32], hb[32];
#pragma unroll
    for (int i = 0; i < 32; i++) { ha[i] = hfa[i]; hb[i] = hfb[i]; }

    l1in2(ha, hb, facta, factb, sm + NS_C + 64 * 64);

    {
        const float4* sa4 = (const float4*)(g_sum + (size_t)nda * 64);
        const float4* sb4 = (const float4*)(g_sum + (size_t)ndb * 64);
#pragma unroll 2
        for (int k4 = 0; k4 < 16; k4++) {
            float4 va = __ldg(sa4 + k4);
            float4 vb = __ldg(sb4 + k4);
            const float* wr = sm + NS_C + (k4 * 4) * 64;
            l1in2(ha, hb, va.x * inva, vb.x * invb, wr);
            l1in2(ha, hb, va.y * inva, vb.y * invb, wr + 64);
            l1in2(ha, hb, va.z * inva, vb.z * invb, wr + 128);
            l1in2(ha, hb, va.w * inva, vb.w * invb, wr + 192);
        }
    }
    if (MOD) {
        float posa = g_pos[nda] * inva;
        float posb = g_pos[ndb] * invb;
        l1in2(ha, hb, posa, posb, sm + NS_W1POS);
    }
    leaky_pack(ha);
    leaky_pack(hb);

    u64 aa[16], ab[16];
    if (PO) {
        float lva = __ldg(level + nda);
        float lvb = __ldg(level + ndb);
        int sa = 0, sb = 0;
#pragma unroll
        for (int k = 0; k < 64; k++) {
            float kn = sm[NS_KN + k];
            sa += (kn < lva) ? 1 : 0;
            sb += (kn < lvb) ? 1 : 0;
        }
        const float4* A4a = (const float4*)(g_A + sa * 128);
        const float4* B4a = (const float4*)(g_B + sa * 128);
        const float4* A4b = (const float4*)(g_A + sb * 128);
        const float4* B4b = (const float4*)(g_B + sb * 128);
        float ra = 0.f, rb = 0.f;
#pragma unroll 1
        for (int c = 0; c < 4; c++) {
            layer2_chunk2<128>(ha, hb, sm + NS_W, sm + NS_BIAS, c * 32, aa, ab);
#pragma unroll
            for (int q = 0; q < 8; q++) {
                int j = c * 32 + q * 4;
                float4 av = __ldg(A4a + c * 8 + q);
                float4 bv = __ldg(B4a + c * 8 + q);
                float x, y;
                unpack2(aa[2 * q], x, y);
                x += fmaf(av.x, lva, bv.x);
                y += fmaf(av.y, lva, bv.y);
                ra += leaky(x) * sm[NS_W2O + j] + leaky(y) * sm[NS_W2O + j + 1];
                unpack2(aa[2 * q + 1], x, y);
                x += fmaf(av.z, lva, bv.z);
                y += fmaf(av.w, lva, bv.w);
                ra += leaky(x) * sm[NS_W2O + j + 2] + leaky(y) * sm[NS_W2O + j + 3];

                float4 av2 = __ldg(A4b + c * 8 + q);
                float4 bv2 = __ldg(B4b + c * 8 + q);
                unpack2(ab[2 * q], x, y);
                x += fmaf(av2.x, lvb, bv2.x);
                y += fmaf(av2.y, lvb, bv2.y);
                rb += leaky(x) * sm[NS_W2O + j] + leaky(y) * sm[NS_W2O + j + 1];
                unpack2(ab[2 * q + 1], x, y);
                x += fmaf(av2.z, lvb, bv2.z);
                y += fmaf(av2.w, lvb, bv2.w);
                rb += leaky(x) * sm[NS_W2O + j + 2] + leaky(y) * sm[NS_W2O + j + 3];
            }
        }
        atomicAdd(out + nda, ra);
        if (v1) atomicAdd(out + ndb, rb);
    } else {
        float* ora = g_h + (size_t)nda * 128;
        float* orb = g_h + (size_t)ndb * 128;
#pragma unroll 1
        for (int c = 0; c < 4; c++) {
            layer2_chunk2<128>(ha, hb, sm + NS_W, sm + NS_BIAS, c * 32, aa, ab);
            u64* oa = (u64*)(ora + c * 32);
#pragma unroll
            for (int i = 0; i < 16; i++) {
                float x, y; unpack2(aa[i], x, y);
                oa[i] = pack2(fmaxf(x, 0.f), fmaxf(y, 0.f));
            }
            if (v1) {
                u64* ob = (u64*)(orb + c * 32);
#pragma unroll
                for (int i = 0; i < 16; i++) {
                    float x, y; unpack2(ab[i], x, y);
                    ob[i] = pack2(fmaxf(x, 0.f), fmaxf(y, 0.f));
                }
            }
        }
    }
}

#define SM_A 8192
#define SM_B 12482
#define SM_B1 16772
#define SM_W2 16836
#define SM_KN 16900
#define OUT_SMEM (16964 * 4)
__global__ void __launch_bounds__(128) k_out(
    const float* __restrict__ o_w1, const float* __restrict__ o_b1,
    const float* __restrict__ o_w2, const float* __restrict__ level,
    float* __restrict__ out)
{
    int half = blockIdx.x & 1;
    int tb = blockIdx.x >> 1;
    int c1 = g_np4[1], c3 = g_np4[3];
    int t1 = (c1 + 255) >> 8;
    int seg, tile, total;
    if (tb < t1) { seg = 1; tile = tb; total = c1; }
    else {
        tb -= t1;
        if (tb >= ((c3 + 255) >> 8)) return;
        seg = 3; tile = tb; total = c3;
    }

    extern __shared__ float sm[];
    for (int i = threadIdx.x; i < 8192; i += 128) {
        int row = i >> 6, col = i & 63;
        sm[i] = o_w1[row * 128 + half * 64 + col];
    }
    for (int i = threadIdx.x; i < 65 * 64; i += 128) {
        int sg = i >> 6, col = i & 63;
        sm[SM_A + sg * 66 + col] = g_A[sg * 128 + half * 64 + col];
        sm[SM_B + sg * 66 + col] = g_B[sg * 128 + half * 64 + col];
    }
    for (int i = threadIdx.x; i < 64; i += 128) {
        sm[SM_B1 + i] = o_b1[half * 64 + i];
        sm[SM_W2 + i] = o_w2[half * 64 + i];
        sm[SM_KN + i] = g_knots[i];
    }
    __syncthreads();

    int p0 = tile * 256 + threadIdx.x;
    if (p0 >= total) return;
    int p1 = p0 + 128;
    bool v1 = p1 < total;
    const int* perm = g_perm4[seg];
    int nd0 = perm[p0];
    int nd1 = v1 ? perm[p1] : nd0;

    float lva = __ldg(level + nd0);
    float lvb = __ldg(level + nd1);
    int sa = 0, sb = 0;
#pragma unroll
    for (int k = 0; k < 64; k++) {
        float kn = sm[SM_KN + k];
        sa += (kn < lva) ? 1 : 0;
        sb += (kn < lvb) ? 1 : 0;
    }

    u64 aa[32], ab[32];
    {
        const float* Aa = sm + SM_A + sa * 66;
        const float* Ba = sm + SM_B + sa * 66;
        const float* Ab = sm + SM_A + sb * 66;
        const float* Bb = sm + SM_B + sb * 66;
        const float* br = sm + SM_B1;
#pragma unroll
        for (int i = 0; i < 32; i++) {
            float a0 = fmaf(Aa[2 * i], lva, br[2 * i] + Ba[2 * i]);
            float a1 = fmaf(Aa[2 * i + 1], lva, br[2 * i + 1] + Ba[2 * i + 1]);
            aa[i] = pack2(a0, a1);
            float b0 = fmaf(Ab[2 * i], lvb, br[2 * i] + Bb[2 * i]);
            float b1 = fmaf(Ab[2 * i + 1], lvb, br[2 * i + 1] + Bb[2 * i + 1]);
            ab[i] = pack2(b0, b1);
        }
    }
    const float4* xa = (const float4*)(g_h + (size_t)nd0 * 128);
    const float4* xb = (const float4*)(g_h + (size_t)nd1 * 128);
#pragma unroll 2
    for (int k4 = 0; k4 < 32; k4++) {
        float4 va = __ldg(xa + k4);
        float4 vb = __ldg(xb + k4);
        const float* wr = sm + (k4 * 4) * 64;
        l1in2(aa, ab, va.x, vb.x, wr);
        l1in2(aa, ab, va.y, vb.y, wr + 64);
        l1in2(aa, ab, va.z, vb.z, wr + 128);
        l1in2(aa, ab, va.w, vb.w, wr + 192);
    }
    float ra = 0.f, rb = 0.f;
#pragma unroll
    for (int i = 0; i < 32; i++) {
        float x, y; unpack2(aa[i], x, y);
        ra += leaky(x) * sm[SM_W2 + 2 * i] + leaky(y) * sm[SM_W2 + 2 * i + 1];
        unpack2(ab[i], x, y);
        rb += leaky(x) * sm[SM_W2 + 2 * i] + leaky(y) * sm[SM_W2 + 2 * i + 1];
    }
    atomicAdd(out + nd0, ra);
    if (v1) atomicAdd(out + nd1, rb);
}

extern "C" void kernel_launch(void* const* d_in, const int* in_sizes, int n_in,
                              void* d_out, int out_size)
{
    const float* feat    = (const float*)d_in[0];
    const float* pi_feat = (const float*)d_in[1];
    const float* level   = (const float*)d_in[2];
    const float* bitpos  = (const float*)d_in[3];

    const int *is_po, *is_module, *src_m, *dst_m, *src_g, *dst_g;
    const float *pi_w1, *pi_b1, *pi_w2, *pi_b2;
    const float *nm_w1, *nm_b1, *nm_w2, *nm_b2;
    const float *ng_w1, *ng_b1, *ng_w2, *ng_b2;
    const float *gw1, *gb1, *gw2, *gb2;
    const float *o_w1, *o_b1, *o_w2, *o_b2;
    int Em, Eg;

    if (in_sizes[4] < 1000) {
        pi_w1 = (const float*)d_in[4];  pi_b1 = (const float*)d_in[5];
        pi_w2 = (const float*)d_in[6];  pi_b2 = (const float*)d_in[7];
        nm_w1 = (const float*)d_in[8];  nm_b1 = (const float*)d_in[9];
        nm_w2 = (const float*)d_in[10]; nm_b2 = (const float*)d_in[11];
        ng_w1 = (const float*)d_in[12]; ng_b1 = (const float*)d_in[13];
        ng_w2 = (const float*)d_in[14]; ng_b2 = (const float*)d_in[15];
        gw1 = (const float*)d_in[16];   gb1 = (const float*)d_in[17];
        gw2 = (const float*)d_in[18];   gb2 = (const float*)d_in[19];
        o_w1 = (const float*)d_in[20];  o_b1 = (const float*)d_in[21];
        o_w2 = (const float*)d_in[22];  o_b2 = (const float*)d_in[23];
        is_po = (const int*)d_in[24];   is_module = (const int*)d_in[25];
        src_m = (const int*)d_in[26];   dst_m = (const int*)d_in[27];
        src_g = (const int*)d_in[28];   dst_g = (const int*)d_in[29];
        Em = in_sizes[26]; Eg = in_sizes[28];
    } else {
        is_po = (const int*)d_in[4];    is_module = (const int*)d_in[5];
        src_m = (const int*)d_in[6];    dst_m = (const int*)d_in[7];
        src_g = (const int*)d_in[8];    dst_g = (const int*)d_in[9];
        pi_w1 = (const float*)d_in[10]; pi_b1 = (const float*)d_in[11];
        pi_w2 = (const float*)d_in[12]; pi_b2 = (const float*)d_in[13];
        nm_w1 = (const float*)d_in[14]; nm_b1 = (const float*)d_in[15];
        nm_w2 = (const float*)d_in[16]; nm_b2 = (const float*)d_in[17];
        ng_w1 = (const float*)d_in[18]; ng_b1 = (const float*)d_in[19];
        ng_w2 = (const float*)d_in[20]; ng_b2 = (const float*)d_in[21];
        gw1 = (const float*)d_in[22];   gb1 = (const float*)d_in[23];
        gw2 = (const float*)d_in[24];   gb2 = (const float*)d_in[25];
        o_w1 = (const float*)d_in[26];  o_b1 = (const float*)d_in[27];
        o_w2 = (const float*)d_in[28];  o_b2 = (const float*)d_in[29];
        Em = in_sizes[6]; Eg = in_sizes[8];
    }

    int n = in_sizes[2];

    static cudaStream_t s2 = nullptr, s3 = nullptr;
    static cudaEvent_t evFork = nullptr, evZero = nullptr, evB = nullptr,
                       evC = nullptr, evE = nullptr, evPO = nullptr;
    if (!s2) {
        cudaStreamCreate(&s2);
        cudaStreamCreate(&s3);
        cudaEventCreateWithFlags(&evFork, cudaEventDisableTiming);
        cudaEventCreateWithFlags(&evZero, cudaEventDisableTiming);
        cudaEventCreateWithFlags(&evB, cudaEventDisableTiming);
        cudaEventCreateWithFlags(&evC, cudaEventDisableTiming);
        cudaEventCreateWithFlags(&evE, cudaEventDisableTiming);
        cudaEventCreateWithFlags(&evPO, cudaEventDisableTiming);
    }

    cudaFuncSetAttribute(k_pre, cudaFuncAttributeMaxDynamicSharedMemorySize, PRE_SMEM);
    cudaFuncSetAttribute(k_feat, cudaFuncAttributeMaxDynamicSharedMemorySize, FEAT_SMEM);
    cudaFuncSetAttribute(k_node_half<true>, cudaFuncAttributeMaxDynamicSharedMemorySize, NODE_SMEM);
    cudaFuncSetAttribute(k_node_half<false>, cudaFuncAttributeMaxDynamicSharedMemorySize, NODE_SMEM);
    cudaFuncSetAttribute(k_out, cudaFuncAttributeMaxDynamicSharedMemorySize, OUT_SMEM);

    int ntile = (n + 255) / 256;
    int npart = (n + 255) / 256;

    void *p_sum, *p_np;
    cudaGetSymbolAddress(&p_sum, g_sum);
    cudaGetSymbolAddress(&p_np, g_np4);

    cudaEventRecord(evFork, 0);
    cudaStreamWaitEvent(s2, evFork, 0);
    cudaStreamWaitEvent(s3, evFork, 0);

    // s3: weight-only composes
    k_compose<<<dim3(65, 2), 64, 0, s3>>>(pi_w2, pi_b2, nm_w1, ng_w1);
    k_compose2<<<dim3(65, 2), 128, 0, s3>>>(nm_w2, nm_b2, ng_w2, ng_b2, o_w1, o_b1);
    cudaEventRecord(evC, s3);

    // s2: zero + partition + feat projection
    cudaMemsetAsync(p_sum, 0, (size_t)n * 64 * 4, s2);
    cudaMemsetAsync(p_np, 0, 16, s2);
    k_part<<<npart, 256, 0, s2>>>(is_module, is_po, n);
    cudaEventRecord(evZero, s2);
    k_feat<<<ntile + 4, 128, FEAT_SMEM, s2>>>(feat, nm_w1, nm_b1, ng_w1, ng_b1);
    cudaEventRecord(evB, s2);

    // main: tables + hid, then edges
    k_pre<<<65 + ntile, 128, PRE_SMEM>>>(
        pi_feat, pi_w1, pi_b1, gw1, gb1, gw2, gb2, o_w1,
        o_b2, (float*)d_out, n);

    cudaStreamWaitEvent(0, evZero, 0);
    long long Etot = (long long)Em + Eg;
    long long hws = (Etot + EPHW - 1) / EPHW;
    int eb = (int)((hws * 16 + 255) / 256);
    k_edges_all<<<eb, 256>>>(src_m, dst_m, src_g, dst_g, bitpos, is_module, Em, Eg);
    cudaEventRecord(evE, 0);   // edges + k_pre complete

    // s2: PO node work (after feat in s2 order; waits on edges + composes)
    cudaStreamWaitEvent(s2, evE, 0);
    cudaStreamWaitEvent(s2, evC, 0);
    k_node_half<true><<<ntile / 2 + 4, 128, NODE_SMEM, s2>>>(
        nm_w1, nm_w2, nm_b2, ng_w2, ng_b2, o_w2, level, (float*)d_out);
    cudaEventRecord(evPO, s2);

    // main: relu node work (needs hidf via evB, composes via evC) -> k_out
    cudaStreamWaitEvent(0, evB, 0);
    cudaStreamWaitEvent(0, evC, 0);
    k_node_half<false><<<ntile / 2 + 4, 128, NODE_SMEM>>>(
        nm_w1, nm_w2, nm_b2, ng_w2, ng_b2, o_w2, level, (float*)d_out);

    k_out<<<(ntile + 2) * 2, 128, OUT_SMEM>>>(
        o_w1, o_b1, o_w2, level, (float*)d_out);

    // join PO work into the captured graph's terminal stream
    cudaStreamWaitEvent(0, evPO, 0);
}